// round 5
// baseline (speedup 1.0000x reference)
#include <cuda_runtime.h>

typedef unsigned long long u64;

#define TT    64
#define BATCH 8192
#define DIN   128
#define BT    64
#define NCTA  (BATCH / BT)

#define G1 128
#define G2 64
#define G3 32
#define H1 32
#define H2 16
#define H3 8

// ---------------- phase A ----------------
#define TPB 8
#define NTA 256
#define WSA 64           // weight tile row width (64 interleaved gate rows)
#define XT_STRIDE 68
#define A_SMEM_FLOATS (DIN * WSA + DIN * XT_STRIDE)   // 8192+8704=16896
#define A_SMEM_BYTES  (A_SMEM_FLOATS * 4)             // 67584 -> 3 CTAs/SM

// ---------------- phase B ----------------
#define NTB 512
#define OFFB_W1H 0        // [32k][128r]
#define OFFB_W2X 4096     // [32k][64r]
#define OFFB_W2H 6144     // [16k][64r]
#define OFFB_B2  7168     // [64]
#define OFFB_W3X 7232     // [16k][32r]
#define OFFB_W3H 7744     // [8k][32r]
#define OFFB_B3  8000     // [32]
#define OFFB_H1  8032     // 2 x [32][64] ping-pong
#define OFFB_H2  12128    // 2 x [16][64]
#define OFFB_H3  14176    // 2 x [8][64]
#define B_SMEM_FLOATS 15200
#define B_SMEM_BYTES  (B_SMEM_FLOATS * 4)

// 256 MB scratch: XG[cta][t][row(4j+q)][bl]  (gate-interleaved rows)
__device__ float g_xg[(size_t)NCTA * TT * G1 * BT];

__device__ __forceinline__ u64 pack2(float a, float b) {
    u64 r;
    asm("mov.b64 %0, {%1, %2};" : "=l"(r) : "f"(a), "f"(b));
    return r;
}
__device__ __forceinline__ u64 fma2(u64 a, u64 b, u64 c) {
    u64 d;
    asm("fma.rn.f32x2 %0, %1, %2, %3;" : "=l"(d) : "l"(a), "l"(b), "l"(c));
    return d;
}
__device__ __forceinline__ float2 u2f2(u64 v) {
    float2 r;
    asm("mov.b64 {%0, %1}, %2;" : "=f"(r.x), "=f"(r.y) : "l"(v));
    return r;
}
__device__ __forceinline__ float sigf(float v) {
    return __fdividef(1.f, 1.f + __expf(-v));
}
__device__ __forceinline__ float tanhf_(float v) {
    return 1.f - __fdividef(2.f, __expf(2.f * v) + 1.f);
}

// acc[GPT gate-rows][NBP batch-pairs] += W[k][g0..] * S[k][b0l..]
template <int WSTR, int SSTR, int GPT, int NBP, int K>
__device__ __forceinline__ void accum(const float* __restrict__ W,
                                      const float* __restrict__ S,
                                      u64 (&acc)[GPT][NBP], int g0, int b0l) {
#pragma unroll 2
    for (int k = 0; k < K; k++) {
        const float* wr = W + k * WSTR + g0;
        float wv[GPT];
        if constexpr (GPT == 4) {
            float4 a = *(const float4*)wr;
            wv[0] = a.x; wv[1] = a.y; wv[2] = a.z; wv[3] = a.w;
        } else {
            float2 a = *(const float2*)wr;
            wv[0] = a.x; wv[1] = a.y;
        }
        const float* sr = S + k * SSTR + b0l;
        u64 xp[NBP];
        if constexpr (NBP == 2) {
            ulonglong2 a = *(const ulonglong2*)sr;
            xp[0] = a.x; xp[1] = a.y;
        } else {
            xp[0] = *(const u64*)sr;
        }
        u64 wd[GPT];
#pragma unroll
        for (int i = 0; i < GPT; i++) wd[i] = pack2(wv[i], wv[i]);
#pragma unroll
        for (int i = 0; i < GPT; i++)
#pragma unroll
            for (int j = 0; j < NBP; j++)
                acc[i][j] = fma2(xp[j], wd[i], acc[i][j]);
    }
}

// ======================= PHASE A =======================
// XG[.., 4j+q, ..] = sum_k x[k] * w_ih1[q*32+j][k] + bias. Block handles 16 j's.
extern __shared__ float smemA[];
__global__ __launch_bounds__(NTA, 3) void lstm_phaseA(
    const float* __restrict__ x,
    const float* __restrict__ w_ih1,
    const float* __restrict__ b_ih1,
    const float* __restrict__ b_hh1) {
    float* WS = smemA;                   // [128k][64r]
    float* XT = smemA + DIN * WSA;       // [128k][68b]
    const int tid = threadIdx.x;
    const int wrp = tid >> 5, ln = tid & 31;
    const int tg  = blockIdx.x;          // timestep group
    const int bg  = blockIdx.y;          // j-half: j in [16bg, 16bg+16)
    const int cta = blockIdx.z;          // batch tile
    const int b0g = cta * BT;

    // stage weights gate-interleaved: local row 4*jl+q <- w_ih1[(16bg+jl)+32q][k]
    for (int idx = tid; idx < 16 * 4 * DIN; idx += NTA) {
        int q = idx >> 11, jl = (idx >> 7) & 15, k = idx & 127;
        int og = bg * 16 + jl + (q << 5);
        WS[k * WSA + 4 * jl + q] = w_ih1[og * DIN + k];
    }
    const int jl = tid >> 4;             // 0..15
    const int b0 = (tid & 15) * 4;
    u64 bd[4];
#pragma unroll
    for (int q = 0; q < 4; q++) {
        int og = bg * 16 + jl + (q << 5);
        float bv = b_ih1[og] + b_hh1[og];
        bd[q] = pack2(bv, bv);
    }

    for (int tt = 0; tt < TPB; tt++) {
        const int t = tg * TPB + tt;
        // stage x tile transposed [k][b]
        for (int r2 = 0; r2 < 8; r2++) {
            int bl = wrp * 8 + r2;
            const float* xrow = x + ((size_t)(b0g + bl) * TT + t) * DIN;
#pragma unroll
            for (int i = 0; i < 4; i++)
                XT[(i * 32 + ln) * XT_STRIDE + bl] = xrow[i * 32 + ln];
        }
        __syncthreads();

        u64 acc[4][2];
#pragma unroll
        for (int q = 0; q < 4; q++) { acc[q][0] = bd[q]; acc[q][1] = bd[q]; }

        accum<WSA, XT_STRIDE, 4, 2, DIN>(WS, XT, acc, 4 * jl, b0);

        float* xgout = g_xg + ((size_t)(cta * TT + t) * G1) * BT;
#pragma unroll
        for (int q = 0; q < 4; q++) {
            ulonglong2 v;
            v.x = acc[q][0]; v.y = acc[q][1];
            *(ulonglong2*)(xgout + (size_t)(bg * 64 + 4 * jl + q) * BT + b0) = v;
        }
        __syncthreads();   // before restaging XT
    }
}

// ======================= PHASE B =======================
extern __shared__ float smemB[];
__global__ __launch_bounds__(NTB, 1) void lstm_phaseB(
    const float* __restrict__ w_hh1,
    const float* __restrict__ w_ih2, const float* __restrict__ w_hh2,
    const float* __restrict__ b_ih2, const float* __restrict__ b_hh2,
    const float* __restrict__ w_ih3, const float* __restrict__ w_hh3,
    const float* __restrict__ b_ih3, const float* __restrict__ b_hh3,
    const float* __restrict__ fc_w, const float* __restrict__ fc_b,
    float* __restrict__ out) {
    const int tid = threadIdx.x;
    const int cta = blockIdx.x;

    float* W1H = smemB + OFFB_W1H;
    float* W2X = smemB + OFFB_W2X;
    float* W2H = smemB + OFFB_W2H;
    float* B2  = smemB + OFFB_B2;
    float* W3X = smemB + OFFB_W3X;
    float* W3H = smemB + OFFB_W3H;
    float* B3  = smemB + OFFB_B3;
    float* H1B = smemB + OFFB_H1;   // 2 x 2048
    float* H2B = smemB + OFFB_H2;   // 2 x 1024
    float* H3B = smemB + OFFB_H3;   // 2 x 512

    // ---- stage weights gate-interleaved [k][4j+q] ----
    for (int i = tid; i < G1 * H1; i += NTB) {
        int g = i >> 5, k = i & 31;
        W1H[k * G1 + 4 * (g & 31) + (g >> 5)] = w_hh1[i];
    }
    for (int i = tid; i < G2 * H1; i += NTB) {
        int g = i >> 5, k = i & 31;
        W2X[k * G2 + 4 * (g & 15) + (g >> 4)] = w_ih2[i];
    }
    for (int i = tid; i < G2 * H2; i += NTB) {
        int g = i >> 4, k = i & 15;
        W2H[k * G2 + 4 * (g & 15) + (g >> 4)] = w_hh2[i];
    }
    for (int i = tid; i < G2; i += NTB)
        B2[4 * (i & 15) + (i >> 4)] = b_ih2[i] + b_hh2[i];
    for (int i = tid; i < G3 * H2; i += NTB) {
        int g = i >> 4, k = i & 15;
        W3X[k * G3 + 4 * (g & 7) + (g >> 3)] = w_ih3[i];
    }
    for (int i = tid; i < G3 * H3; i += NTB) {
        int g = i >> 3, k = i & 7;
        W3H[k * G3 + 4 * (g & 7) + (g >> 3)] = w_hh3[i];
    }
    for (int i = tid; i < G3; i += NTB)
        B3[4 * (i & 7) + (i >> 3)] = b_ih3[i] + b_hh3[i];
    // zero both ping-pong h buffers
    for (int i = tid; i < 2 * H1 * BT; i += NTB) H1B[i] = 0.f;
    for (int i = tid; i < 2 * H2 * BT; i += NTB) H2B[i] = 0.f;
    for (int i = tid; i < 2 * H3 * BT; i += NTB) H3B[i] = 0.f;

    // fixed ownership -> cell states live in registers
    const int j1 = tid >> 4, b1 = (tid & 15) * 4;   // L1: j x 4 batch
    const int j2 = tid >> 5, b2 = (tid & 31) * 2;   // L2: j x 2 batch
    const int j3 = tid >> 6, b3 = tid & 63;         // L3: j x 1 batch
    float c1[4] = {0.f, 0.f, 0.f, 0.f};
    float c2[2] = {0.f, 0.f};
    float c3 = 0.f;

    const float* xgbase = g_xg + (size_t)cta * TT * G1 * BT;

    // prefetch XG(t=0): rows 4j1+q, batch cols b1..b1+3
    ulonglong2 xga[4];
#pragma unroll
    for (int q = 0; q < 4; q++)
        xga[q] = *(const ulonglong2*)(xgbase + (size_t)(4 * j1 + q) * BT + b1);

    __syncthreads();

    for (int t = 0; t < TT; ++t) {
        const int r = t & 1;
        float* H1r = H1B + r * (H1 * BT);
        float* H1w = H1B + (1 - r) * (H1 * BT);
        float* H2r = H2B + r * (H2 * BT);
        float* H2w = H2B + (1 - r) * (H2 * BT);
        float* H3r = H3B + r * (H3 * BT);
        float* H3w = H3B + (1 - r) * (H3 * BT);

        // ---- stage 1: layer-1 gates + ew fused ----
        {
            u64 acc[4][2];
#pragma unroll
            for (int q = 0; q < 4; q++) { acc[q][0] = xga[q].x; acc[q][1] = xga[q].y; }
            accum<G1, BT, 4, 2, H1>(W1H, H1r, acc, 4 * j1, b1);
            if (t + 1 < TT) {
#pragma unroll
                for (int q = 0; q < 4; q++)
                    xga[q] = *(const ulonglong2*)(xgbase +
                        (size_t)((t + 1) * G1 + 4 * j1 + q) * BT + b1);
            }
            float h4[4];
#pragma unroll
            for (int m = 0; m < 4; m++) {
                float2 a0 = u2f2(acc[0][m >> 1]);
                float2 a1 = u2f2(acc[1][m >> 1]);
                float2 a2 = u2f2(acc[2][m >> 1]);
                float2 a3 = u2f2(acc[3][m >> 1]);
                float iv = sigf((m & 1) ? a0.y : a0.x);
                float fv = sigf((m & 1) ? a1.y : a1.x);
                float gv = tanhf_((m & 1) ? a2.y : a2.x);
                float ov = sigf((m & 1) ? a3.y : a3.x);
                float c = fv * c1[m] + iv * gv;
                c1[m] = c;
                h4[m] = ov * tanhf_(c);
            }
            float4 hv; hv.x = h4[0]; hv.y = h4[1]; hv.z = h4[2]; hv.w = h4[3];
            *(float4*)(H1w + j1 * BT + b1) = hv;
        }
        __syncthreads();

        // ---- stage 2: layer-2 gates + ew fused ----
        {
            u64 acc[4][1];
#pragma unroll
            for (int q = 0; q < 4; q++) {
                float bv = B2[4 * j2 + q];
                acc[q][0] = pack2(bv, bv);
            }
            accum<G2, BT, 4, 1, H1>(W2X, H1w, acc, 4 * j2, b2);
            accum<G2, BT, 4, 1, H2>(W2H, H2r, acc, 4 * j2, b2);
            float2 a0 = u2f2(acc[0][0]);
            float2 a1 = u2f2(acc[1][0]);
            float2 a2 = u2f2(acc[2][0]);
            float2 a3 = u2f2(acc[3][0]);
            float h2v[2];
#pragma unroll
            for (int m = 0; m < 2; m++) {
                float iv = sigf(m ? a0.y : a0.x);
                float fv = sigf(m ? a1.y : a1.x);
                float gv = tanhf_(m ? a2.y : a2.x);
                float ov = sigf(m ? a3.y : a3.x);
                float c = fv * c2[m] + iv * gv;
                c2[m] = c;
                h2v[m] = ov * tanhf_(c);
            }
            float2 hv; hv.x = h2v[0]; hv.y = h2v[1];
            *(float2*)(H2w + j2 * BT + b2) = hv;
        }
        __syncthreads();

        // ---- stage 3: layer-3 gates + ew fused (gate-pair f32x2) ----
        {
            u64 aif = *(const u64*)(B3 + 4 * j3);
            u64 ago = *(const u64*)(B3 + 4 * j3 + 2);
#pragma unroll 2
            for (int k = 0; k < H2; k++) {
                ulonglong2 w = *(const ulonglong2*)(W3X + k * G3 + 4 * j3);
                float s = H2w[k * BT + b3];
                u64 ss = pack2(s, s);
                aif = fma2(ss, w.x, aif);
                ago = fma2(ss, w.y, ago);
            }
#pragma unroll
            for (int k = 0; k < H3; k++) {
                ulonglong2 w = *(const ulonglong2*)(W3H + k * G3 + 4 * j3);
                float s = H3r[k * BT + b3];
                u64 ss = pack2(s, s);
                aif = fma2(ss, w.x, aif);
                ago = fma2(ss, w.y, ago);
            }
            float2 vif = u2f2(aif), vgo = u2f2(ago);
            float iv = sigf(vif.x);
            float fv = sigf(vif.y);
            float gv = tanhf_(vgo.x);
            float ov = sigf(vgo.y);
            float c = fv * c3 + iv * gv;
            c3 = c;
            H3w[j3 * BT + b3] = ov * tanhf_(c);
        }
        __syncthreads();
    }

    // final FC: last write was buffer 0 (TT even)
    if (tid < BT) {
        const float* H3f = H3B;   // buffer 0
        float acc = fc_b[0];
#pragma unroll
        for (int j = 0; j < H3; j++) acc += fc_w[j] * H3f[j * BT + tid];
        out[cta * BT + tid] = acc;
    }
}

extern "C" void kernel_launch(void* const* d_in, const int* in_sizes, int n_in,
                              void* d_out, int out_size) {
    (void)in_sizes; (void)n_in; (void)out_size;
    const float* x     = (const float*)d_in[0];
    const float* w_ih1 = (const float*)d_in[1];
    const float* w_hh1 = (const float*)d_in[2];
    const float* b_ih1 = (const float*)d_in[3];
    const float* b_hh1 = (const float*)d_in[4];
    const float* w_ih2 = (const float*)d_in[5];
    const float* w_hh2 = (const float*)d_in[6];
    const float* b_ih2 = (const float*)d_in[7];
    const float* b_hh2 = (const float*)d_in[8];
    const float* w_ih3 = (const float*)d_in[9];
    const float* w_hh3 = (const float*)d_in[10];
    const float* b_ih3 = (const float*)d_in[11];
    const float* b_hh3 = (const float*)d_in[12];
    const float* fc_w  = (const float*)d_in[13];
    const float* fc_b  = (const float*)d_in[14];
    float* out = (float*)d_out;

    cudaFuncSetAttribute(lstm_phaseA,
                         cudaFuncAttributeMaxDynamicSharedMemorySize, A_SMEM_BYTES);
    cudaFuncSetAttribute(lstm_phaseB,
                         cudaFuncAttributeMaxDynamicSharedMemorySize, B_SMEM_BYTES);

    dim3 gridA(TT / TPB, 2, NCTA);
    lstm_phaseA<<<gridA, NTA, A_SMEM_BYTES>>>(x, w_ih1, b_ih1, b_hh1);
    lstm_phaseB<<<NCTA, NTB, B_SMEM_BYTES>>>(
        w_hh1, w_ih2, w_hh2, b_ih2, b_hh2,
        w_ih3, w_hh3, b_ih3, b_hh3, fc_w, fc_b, out);
}

// round 6
// speedup vs baseline: 1.0842x; 1.0842x over previous
#include <cuda_runtime.h>

typedef unsigned long long u64;

#define TT    64
#define BATCH 8192
#define DIN   128
#define BT    64
#define NCTA  (BATCH / BT)

#define G1 128
#define G2 64
#define G3 32
#define H1 32
#define H2 16
#define H3 8

// ---------------- phase A ----------------
#define TPB 8
#define NTA 256
#define WSTRA 132        // weight row stride (16B-aligned, 4-way-stage ok)
#define XSTR 68          // x tile row stride
#define A_SMEM_FLOATS (DIN * WSTRA + DIN * XSTR)   // 16896+8704=25600
#define A_SMEM_BYTES  (A_SMEM_FLOATS * 4)          // 102400 -> 2 CTAs/SM

// ---------------- phase B ----------------
#define NTB 512
// smem float offsets (all 16B aligned)
#define OFFB_W1HD 0        // dup [32k][256]
#define OFFB_W2XD 8192     // dup [32k][128]
#define OFFB_W2HD 12288    // dup [16k][128]
#define OFFB_B2I  14336    // [64] interleaved
#define OFFB_W3XI 14400    // [16k][32] interleaved
#define OFFB_W3HI 14912    // [8k][32]
#define OFFB_B3I  15168    // [32]
#define OFFB_H1   15200    // 2 x [32][64]
#define OFFB_H2   19296    // 2 x [16][64]
#define OFFB_H3   21344    // 2 x [8][64]
#define B_SMEM_FLOATS 22368
#define B_SMEM_BYTES  (B_SMEM_FLOATS * 4)

// 256 MB scratch: XG[cta][t][row(4j+q)][bl]  (gate-interleaved rows)
__device__ float g_xg[(size_t)NCTA * TT * G1 * BT];

__device__ __forceinline__ u64 pack2(float a, float b) {
    u64 r;
    asm("mov.b64 %0, {%1, %2};" : "=l"(r) : "f"(a), "f"(b));
    return r;
}
__device__ __forceinline__ u64 fma2(u64 a, u64 b, u64 c) {
    u64 d;
    asm("fma.rn.f32x2 %0, %1, %2, %3;" : "=l"(d) : "l"(a), "l"(b), "l"(c));
    return d;
}
__device__ __forceinline__ float2 u2f2(u64 v) {
    float2 r;
    asm("mov.b64 {%0, %1}, %2;" : "=f"(r.x), "=f"(r.y) : "l"(v));
    return r;
}
__device__ __forceinline__ float sigf(float v) {
    return __fdividef(1.f, 1.f + __expf(-v));
}
__device__ __forceinline__ float tanhf_(float v) {
    return 1.f - __fdividef(2.f, __expf(2.f * v) + 1.f);
}

// ======================= PHASE A =======================
// XG[.., 4j+q, ..] = sum_k x[k] * w_ih1[q*32+j][k] + b1[q*32+j]
extern __shared__ float smemA[];
__global__ __launch_bounds__(NTA, 2) void lstm_phaseA(
    const float* __restrict__ x,
    const float* __restrict__ w_ih1,
    const float* __restrict__ b_ih1,
    const float* __restrict__ b_hh1) {
    float* WS = smemA;                   // [128k][WSTRA]
    float* XT = smemA + DIN * WSTRA;     // [128k][XSTR]
    const int tid = threadIdx.x;
    const int wrp = tid >> 5, ln = tid & 31;
    const int tg  = blockIdx.x;
    const int cta = blockIdx.y;
    const int b0g = cta * BT;
    const int t0  = tg * TPB;

    // stage weights gate-interleaved: WS[k][4j+q] <- w_ih1[q*32+j][k]
    for (int idx = tid; idx < G1 * DIN; idx += NTA) {
        int rr = idx >> 7, k = idx & 127;
        int g = ((rr & 3) << 5) + (rr >> 2);
        WS[k * WSTRA + rr] = w_ih1[g * DIN + k];
    }
    const int g0 = (tid >> 4) * 8;       // 8 interleaved rows
    const int b0l = (tid & 15) * 4;      // 4 batch cols
    u64 bd[8];
#pragma unroll
    for (int i = 0; i < 8; i++) {
        int rr = g0 + i;
        int g = ((rr & 3) << 5) + (rr >> 2);
        float bv = b_ih1[g] + b_hh1[g];
        bd[i] = pack2(bv, bv);
    }

    // x prefetch registers: thread stages rows [wrp*8, wrp*8+8), k = i*32+ln
    float xr[32];
#define LOADX(t)                                                            \
    {                                                                       \
        _Pragma("unroll") for (int r2 = 0; r2 < 8; r2++) {                  \
            const float* xrow = x +                                         \
                ((size_t)(b0g + wrp * 8 + r2) * TT + (t)) * DIN;            \
            _Pragma("unroll") for (int i = 0; i < 4; i++)                   \
                xr[r2 * 4 + i] = xrow[i * 32 + ln];                         \
        }                                                                   \
    }
#define STOREX()                                                            \
    {                                                                       \
        _Pragma("unroll") for (int r2 = 0; r2 < 8; r2++)                    \
            _Pragma("unroll") for (int i = 0; i < 4; i++)                   \
                XT[(i * 32 + ln) * XSTR + wrp * 8 + r2] = xr[r2 * 4 + i];   \
    }

    LOADX(t0);
    __syncthreads();        // weights staged
    STOREX();
    __syncthreads();        // XT(t0) ready

    for (int tt = 0; tt < TPB; tt++) {
        const int t = t0 + tt;
        if (tt + 1 < TPB) LOADX(t + 1);   // LDG overlapped with compute

        u64 acc[8][2];
#pragma unroll
        for (int i = 0; i < 8; i++) { acc[i][0] = bd[i]; acc[i][1] = bd[i]; }

#pragma unroll 2
        for (int k = 0; k < DIN; k++) {
            const float* wr = WS + k * WSTRA + g0;
            float4 wa = *(const float4*)wr;
            float4 wb = *(const float4*)(wr + 4);
            ulonglong2 xv = *(const ulonglong2*)(XT + k * XSTR + b0l);
            u64 wd[8];
            wd[0] = pack2(wa.x, wa.x); wd[1] = pack2(wa.y, wa.y);
            wd[2] = pack2(wa.z, wa.z); wd[3] = pack2(wa.w, wa.w);
            wd[4] = pack2(wb.x, wb.x); wd[5] = pack2(wb.y, wb.y);
            wd[6] = pack2(wb.z, wb.z); wd[7] = pack2(wb.w, wb.w);
#pragma unroll
            for (int i = 0; i < 8; i++) {
                acc[i][0] = fma2(xv.x, wd[i], acc[i][0]);
                acc[i][1] = fma2(xv.y, wd[i], acc[i][1]);
            }
        }

        float* xgout = g_xg + ((size_t)(cta * TT + t) * G1) * BT;
#pragma unroll
        for (int i = 0; i < 8; i++) {
            ulonglong2 v;
            v.x = acc[i][0]; v.y = acc[i][1];
            *(ulonglong2*)(xgout + (size_t)(g0 + i) * BT + b0l) = v;
        }
        __syncthreads();    // all done reading XT
        if (tt + 1 < TPB) { STOREX(); }
        __syncthreads();    // XT(tt+1) ready
    }
}

// ======================= PHASE B =======================
extern __shared__ float smemB[];
__global__ __launch_bounds__(NTB, 1) void lstm_phaseB(
    const float* __restrict__ w_hh1,
    const float* __restrict__ w_ih2, const float* __restrict__ w_hh2,
    const float* __restrict__ b_ih2, const float* __restrict__ b_hh2,
    const float* __restrict__ w_ih3, const float* __restrict__ w_hh3,
    const float* __restrict__ b_ih3, const float* __restrict__ b_hh3,
    const float* __restrict__ fc_w, const float* __restrict__ fc_b,
    float* __restrict__ out) {
    const int tid = threadIdx.x;
    const int cta = blockIdx.x;

    float* W1HD = smemB + OFFB_W1HD;
    float* W2XD = smemB + OFFB_W2XD;
    float* W2HD = smemB + OFFB_W2HD;
    float* B2I  = smemB + OFFB_B2I;
    float* W3XI = smemB + OFFB_W3XI;
    float* W3HI = smemB + OFFB_W3HI;
    float* B3I  = smemB + OFFB_B3I;
    float* H1B  = smemB + OFFB_H1;
    float* H2B  = smemB + OFFB_H2;
    float* H3B  = smemB + OFFB_H3;

    // ---- stage weights: interleaved rows, W1H/W2X/W2H duplicated ----
    for (int i = tid; i < G1 * H1; i += NTB) {
        int g = i >> 5, k = i & 31;
        int rr = 4 * (g & 31) + (g >> 5);
        float v = w_hh1[i];
        W1HD[k * 256 + 2 * rr] = v; W1HD[k * 256 + 2 * rr + 1] = v;
    }
    for (int i = tid; i < G2 * H1; i += NTB) {
        int g = i >> 5, k = i & 31;
        int rr = 4 * (g & 15) + (g >> 4);
        float v = w_ih2[i];
        W2XD[k * 128 + 2 * rr] = v; W2XD[k * 128 + 2 * rr + 1] = v;
    }
    for (int i = tid; i < G2 * H2; i += NTB) {
        int g = i >> 4, k = i & 15;
        int rr = 4 * (g & 15) + (g >> 4);
        float v = w_hh2[i];
        W2HD[k * 128 + 2 * rr] = v; W2HD[k * 128 + 2 * rr + 1] = v;
    }
    for (int i = tid; i < G2; i += NTB)
        B2I[4 * (i & 15) + (i >> 4)] = b_ih2[i] + b_hh2[i];
    for (int i = tid; i < G3 * H2; i += NTB) {
        int g = i >> 4, k = i & 15;
        W3XI[k * 32 + 4 * (g & 7) + (g >> 3)] = w_ih3[i];
    }
    for (int i = tid; i < G3 * H3; i += NTB) {
        int g = i >> 3, k = i & 7;
        W3HI[k * 32 + 4 * (g & 7) + (g >> 3)] = w_hh3[i];
    }
    for (int i = tid; i < G3; i += NTB)
        B3I[4 * (i & 7) + (i >> 3)] = b_ih3[i] + b_hh3[i];
    for (int i = tid; i < 2 * H1 * BT; i += NTB) H1B[i] = 0.f;
    for (int i = tid; i < 2 * H2 * BT; i += NTB) H2B[i] = 0.f;
    for (int i = tid; i < 2 * H3 * BT; i += NTB) H3B[i] = 0.f;

    // stage mappings (all 512 threads active in every stage)
    const int j1 = tid >> 4, b1 = (tid & 15) * 4;   // L1: 1 j x 4 batch
    const int j2 = tid >> 5, b2 = (tid & 31) * 2;   // L2: 1 j x 2 batch
    const int j3 = tid >> 6, b3 = tid & 63;         // L3: 1 j x 1 batch
    float c1[4] = {0.f, 0.f, 0.f, 0.f};
    float c2[2] = {0.f, 0.f};
    float c3 = 0.f;

    const float* xgbase = g_xg + (size_t)cta * TT * G1 * BT;

    ulonglong2 xga[4];
#pragma unroll
    for (int q = 0; q < 4; q++)
        xga[q] = *(const ulonglong2*)(xgbase + (size_t)(4 * j1 + q) * BT + b1);

    __syncthreads();

    for (int t = 0; t < TT; ++t) {
        const int r = t & 1;
        float* H1r = H1B + r * (H1 * BT);
        float* H1w = H1B + (1 - r) * (H1 * BT);
        float* H2r = H2B + r * (H2 * BT);
        float* H2w = H2B + (1 - r) * (H2 * BT);
        float* H3r = H3B + r * (H3 * BT);
        float* H3w = H3B + (1 - r) * (H3 * BT);

        // ---- stage 1: L1 gates (dup weights, no packs) + fused ew ----
        {
            u64 acc[4][2];
#pragma unroll
            for (int q = 0; q < 4; q++) { acc[q][0] = xga[q].x; acc[q][1] = xga[q].y; }
#pragma unroll 4
            for (int k = 0; k < H1; k++) {
                const float* wr = W1HD + k * 256 + j1 * 8;
                ulonglong2 wa = *(const ulonglong2*)wr;        // gates 0,1 dup
                ulonglong2 wb = *(const ulonglong2*)(wr + 4);  // gates 2,3 dup
                ulonglong2 xv = *(const ulonglong2*)(H1r + k * BT + b1);
                acc[0][0] = fma2(xv.x, wa.x, acc[0][0]);
                acc[0][1] = fma2(xv.y, wa.x, acc[0][1]);
                acc[1][0] = fma2(xv.x, wa.y, acc[1][0]);
                acc[1][1] = fma2(xv.y, wa.y, acc[1][1]);
                acc[2][0] = fma2(xv.x, wb.x, acc[2][0]);
                acc[2][1] = fma2(xv.y, wb.x, acc[2][1]);
                acc[3][0] = fma2(xv.x, wb.y, acc[3][0]);
                acc[3][1] = fma2(xv.y, wb.y, acc[3][1]);
            }
            if (t + 1 < TT) {
#pragma unroll
                for (int q = 0; q < 4; q++)
                    xga[q] = *(const ulonglong2*)(xgbase +
                        (size_t)((t + 1) * G1 + 4 * j1 + q) * BT + b1);
            }
            float h4[4];
#pragma unroll
            for (int p = 0; p < 2; p++) {
                float2 ai = u2f2(acc[0][p]);
                float2 af = u2f2(acc[1][p]);
                float2 ag = u2f2(acc[2][p]);
                float2 ao = u2f2(acc[3][p]);
#pragma unroll
                for (int m = 0; m < 2; m++) {
                    int e = 2 * p + m;
                    float iv = sigf(m ? ai.y : ai.x);
                    float fv = sigf(m ? af.y : af.x);
                    float gv = tanhf_(m ? ag.y : ag.x);
                    float ov = sigf(m ? ao.y : ao.x);
                    float c = fv * c1[e] + iv * gv;
                    c1[e] = c;
                    h4[e] = ov * tanhf_(c);
                }
            }
            float4 hv; hv.x = h4[0]; hv.y = h4[1]; hv.z = h4[2]; hv.w = h4[3];
            *(float4*)(H1w + j1 * BT + b1) = hv;
        }
        __syncthreads();

        // ---- stage 2: L2 gates + fused ew ----
        {
            u64 acc[4];
            float4 bv4 = *(const float4*)(B2I + j2 * 4);
            acc[0] = pack2(bv4.x, bv4.x);
            acc[1] = pack2(bv4.y, bv4.y);
            acc[2] = pack2(bv4.z, bv4.z);
            acc[3] = pack2(bv4.w, bv4.w);
#pragma unroll 4
            for (int k = 0; k < H1; k++) {
                const float* wr = W2XD + k * 128 + j2 * 8;
                ulonglong2 wa = *(const ulonglong2*)wr;
                ulonglong2 wb = *(const ulonglong2*)(wr + 4);
                u64 xv = *(const u64*)(H1w + k * BT + b2);
                acc[0] = fma2(xv, wa.x, acc[0]);
                acc[1] = fma2(xv, wa.y, acc[1]);
                acc[2] = fma2(xv, wb.x, acc[2]);
                acc[3] = fma2(xv, wb.y, acc[3]);
            }
#pragma unroll 4
            for (int k = 0; k < H2; k++) {
                const float* wr = W2HD + k * 128 + j2 * 8;
                ulonglong2 wa = *(const ulonglong2*)wr;
                ulonglong2 wb = *(const ulonglong2*)(wr + 4);
                u64 xv = *(const u64*)(H2r + k * BT + b2);
                acc[0] = fma2(xv, wa.x, acc[0]);
                acc[1] = fma2(xv, wa.y, acc[1]);
                acc[2] = fma2(xv, wb.x, acc[2]);
                acc[3] = fma2(xv, wb.y, acc[3]);
            }
            float2 ai = u2f2(acc[0]);
            float2 af = u2f2(acc[1]);
            float2 ag = u2f2(acc[2]);
            float2 ao = u2f2(acc[3]);
            float h2v[2];
#pragma unroll
            for (int m = 0; m < 2; m++) {
                float iv = sigf(m ? ai.y : ai.x);
                float fv = sigf(m ? af.y : af.x);
                float gv = tanhf_(m ? ag.y : ag.x);
                float ov = sigf(m ? ao.y : ao.x);
                float c = fv * c2[m] + iv * gv;
                c2[m] = c;
                h2v[m] = ov * tanhf_(c);
            }
            float2 hv; hv.x = h2v[0]; hv.y = h2v[1];
            *(float2*)(H2w + j2 * BT + b2) = hv;
        }
        __syncthreads();

        // ---- stage 3: L3 gates (gate-pair f32x2) + fused ew ----
        {
            u64 aif = *(const u64*)(B3I + 4 * j3);
            u64 ago = *(const u64*)(B3I + 4 * j3 + 2);
#pragma unroll 4
            for (int k = 0; k < H2; k++) {
                ulonglong2 w = *(const ulonglong2*)(W3XI + k * G3 + 4 * j3);
                float s = H2w[k * BT + b3];
                u64 ss = pack2(s, s);
                aif = fma2(ss, w.x, aif);
                ago = fma2(ss, w.y, ago);
            }
#pragma unroll
            for (int k = 0; k < H3; k++) {
                ulonglong2 w = *(const ulonglong2*)(W3HI + k * G3 + 4 * j3);
                float s = H3r[k * BT + b3];
                u64 ss = pack2(s, s);
                aif = fma2(ss, w.x, aif);
                ago = fma2(ss, w.y, ago);
            }
            float2 vif = u2f2(aif), vgo = u2f2(ago);
            float iv = sigf(vif.x);
            float fv = sigf(vif.y);
            float gv = tanhf_(vgo.x);
            float ov = sigf(vgo.y);
            float c = fv * c3 + iv * gv;
            c3 = c;
            H3w[j3 * BT + b3] = ov * tanhf_(c);
        }
        __syncthreads();
    }

    // final FC: last write (t=63, r=1) went to buffer 0
    if (tid < BT) {
        const float* H3f = H3B;
        float acc = fc_b[0];
#pragma unroll
        for (int j = 0; j < H3; j++) acc += fc_w[j] * H3f[j * BT + tid];
        out[cta * BT + tid] = acc;
    }
}

extern "C" void kernel_launch(void* const* d_in, const int* in_sizes, int n_in,
                              void* d_out, int out_size) {
    (void)in_sizes; (void)n_in; (void)out_size;
    const float* x     = (const float*)d_in[0];
    const float* w_ih1 = (const float*)d_in[1];
    const float* w_hh1 = (const float*)d_in[2];
    const float* b_ih1 = (const float*)d_in[3];
    const float* b_hh1 = (const float*)d_in[4];
    const float* w_ih2 = (const float*)d_in[5];
    const float* w_hh2 = (const float*)d_in[6];
    const float* b_ih2 = (const float*)d_in[7];
    const float* b_hh2 = (const float*)d_in[8];
    const float* w_ih3 = (const float*)d_in[9];
    const float* w_hh3 = (const float*)d_in[10];
    const float* b_ih3 = (const float*)d_in[11];
    const float* b_hh3 = (const float*)d_in[12];
    const float* fc_w  = (const float*)d_in[13];
    const float* fc_b  = (const float*)d_in[14];
    float* out = (float*)d_out;

    cudaFuncSetAttribute(lstm_phaseA,
                         cudaFuncAttributeMaxDynamicSharedMemorySize, A_SMEM_BYTES);
    cudaFuncSetAttribute(lstm_phaseB,
                         cudaFuncAttributeMaxDynamicSharedMemorySize, B_SMEM_BYTES);

    dim3 gridA(TT / TPB, NCTA);
    lstm_phaseA<<<gridA, NTA, A_SMEM_BYTES>>>(x, w_ih1, b_ih1, b_hh1);
    lstm_phaseB<<<NCTA, NTB, B_SMEM_BYTES>>>(
        w_hh1, w_ih2, w_hh2, b_ih2, b_hh2,
        w_ih3, w_hh3, b_ih3, b_hh3, fc_w, fc_b, out);
}

// round 7
// speedup vs baseline: 1.2316x; 1.1360x over previous
#include <cuda_runtime.h>

typedef unsigned long long u64;

#define TT    64
#define BATCH 8192
#define DIN   128
#define BT    64
#define NCTA  (BATCH / BT)

#define G1 128
#define G2 64
#define G3 32
#define H1 32
#define H2 16
#define H3 8

// ---------------- phase A ----------------
#define TPB 8
#define NTA 256
#define WSTRA 132
#define XSTR 68
#define A_SMEM_FLOATS (DIN * WSTRA + DIN * XSTR)
#define A_SMEM_BYTES  (A_SMEM_FLOATS * 4)

// ---------------- phase B ----------------
#define NTB 512
#define OFFB_W1HI 0        // [32k][128]
#define OFFB_W2XI 4096     // [32k][64]
#define OFFB_W2HI 6144     // [16k][64]
#define OFFB_B2I  7168     // [64]
#define OFFB_W3XI 7232     // [16k][32]
#define OFFB_W3HI 7744     // [8k][32]
#define OFFB_B3I  8000     // [32]
#define OFFB_H1   8032     // 2 x [32][64]
#define OFFB_H2   12128    // 2 x [16][64]
#define OFFB_H3   14176    // 2 x [8][64]
#define B_SMEM_FLOATS 15200
#define B_SMEM_BYTES  (B_SMEM_FLOATS * 4)

// 256 MB scratch: XG[cta][t][row(4j+q)][bl]
__device__ float g_xg[(size_t)NCTA * TT * G1 * BT];

__device__ __forceinline__ u64 pack2(float a, float b) {
    u64 r;
    asm("mov.b64 %0, {%1, %2};" : "=l"(r) : "f"(a), "f"(b));
    return r;
}
__device__ __forceinline__ u64 fma2(u64 a, u64 b, u64 c) {
    u64 d;
    asm("fma.rn.f32x2 %0, %1, %2, %3;" : "=l"(d) : "l"(a), "l"(b), "l"(c));
    return d;
}
__device__ __forceinline__ float2 u2f2(u64 v) {
    float2 r;
    asm("mov.b64 {%0, %1}, %2;" : "=f"(r.x), "=f"(r.y) : "l"(v));
    return r;
}
__device__ __forceinline__ float sigf(float v) {
    return __fdividef(1.f, 1.f + __expf(-v));
}
__device__ __forceinline__ float tanhf_(float v) {
    return 1.f - __fdividef(2.f, __expf(2.f * v) + 1.f);
}

// ======================= PHASE A (unchanged from R6) =======================
extern __shared__ float smemA[];
__global__ __launch_bounds__(NTA, 2) void lstm_phaseA(
    const float* __restrict__ x,
    const float* __restrict__ w_ih1,
    const float* __restrict__ b_ih1,
    const float* __restrict__ b_hh1) {
    float* WS = smemA;
    float* XT = smemA + DIN * WSTRA;
    const int tid = threadIdx.x;
    const int wrp = tid >> 5, ln = tid & 31;
    const int tg  = blockIdx.x;
    const int cta = blockIdx.y;
    const int b0g = cta * BT;
    const int t0  = tg * TPB;

    for (int idx = tid; idx < G1 * DIN; idx += NTA) {
        int rr = idx >> 7, k = idx & 127;
        int g = ((rr & 3) << 5) + (rr >> 2);
        WS[k * WSTRA + rr] = w_ih1[g * DIN + k];
    }
    const int g0 = (tid >> 4) * 8;
    const int b0l = (tid & 15) * 4;
    u64 bd[8];
#pragma unroll
    for (int i = 0; i < 8; i++) {
        int rr = g0 + i;
        int g = ((rr & 3) << 5) + (rr >> 2);
        float bv = b_ih1[g] + b_hh1[g];
        bd[i] = pack2(bv, bv);
    }

    float xr[32];
#define LOADX(t)                                                            \
    {                                                                       \
        _Pragma("unroll") for (int r2 = 0; r2 < 8; r2++) {                  \
            const float* xrow = x +                                         \
                ((size_t)(b0g + wrp * 8 + r2) * TT + (t)) * DIN;            \
            _Pragma("unroll") for (int i = 0; i < 4; i++)                   \
                xr[r2 * 4 + i] = xrow[i * 32 + ln];                         \
        }                                                                   \
    }
#define STOREX()                                                            \
    {                                                                       \
        _Pragma("unroll") for (int r2 = 0; r2 < 8; r2++)                    \
            _Pragma("unroll") for (int i = 0; i < 4; i++)                   \
                XT[(i * 32 + ln) * XSTR + wrp * 8 + r2] = xr[r2 * 4 + i];   \
    }

    LOADX(t0);
    __syncthreads();
    STOREX();
    __syncthreads();

    for (int tt = 0; tt < TPB; tt++) {
        const int t = t0 + tt;
        if (tt + 1 < TPB) LOADX(t + 1);

        u64 acc[8][2];
#pragma unroll
        for (int i = 0; i < 8; i++) { acc[i][0] = bd[i]; acc[i][1] = bd[i]; }

#pragma unroll 2
        for (int k = 0; k < DIN; k++) {
            const float* wr = WS + k * WSTRA + g0;
            float4 wa = *(const float4*)wr;
            float4 wb = *(const float4*)(wr + 4);
            ulonglong2 xv = *(const ulonglong2*)(XT + k * XSTR + b0l);
            u64 wd[8];
            wd[0] = pack2(wa.x, wa.x); wd[1] = pack2(wa.y, wa.y);
            wd[2] = pack2(wa.z, wa.z); wd[3] = pack2(wa.w, wa.w);
            wd[4] = pack2(wb.x, wb.x); wd[5] = pack2(wb.y, wb.y);
            wd[6] = pack2(wb.z, wb.z); wd[7] = pack2(wb.w, wb.w);
#pragma unroll
            for (int i = 0; i < 8; i++) {
                acc[i][0] = fma2(xv.x, wd[i], acc[i][0]);
                acc[i][1] = fma2(xv.y, wd[i], acc[i][1]);
            }
        }

        float* xgout = g_xg + ((size_t)(cta * TT + t) * G1) * BT;
#pragma unroll
        for (int i = 0; i < 8; i++) {
            ulonglong2 v;
            v.x = acc[i][0]; v.y = acc[i][1];
            *(ulonglong2*)(xgout + (size_t)(g0 + i) * BT + b0l) = v;
        }
        __syncthreads();
        if (tt + 1 < TPB) { STOREX(); }
        __syncthreads();
    }
}

// ======================= PHASE B (pipelined) =======================
// Warps 0-7 (A): layer-1 recurrence, one step ahead.
// Warps 8-15 (B): layers 2+3.
// h_x(t) lives in buffer (t&1).

__device__ __forceinline__ void stage1_step(
    int tn, const float* __restrict__ xgbase, const float* __restrict__ W1HI,
    float* __restrict__ H1B, ulonglong2 (&xga)[4][2], float (&c1)[8],
    int j1, int b1) {
    const float* H1r = H1B + (((tn + 1) & 1) << 11);   // h1(tn-1)
    float* H1w = H1B + ((tn & 1) << 11);               // h1(tn)

    u64 acc[4][4];
#pragma unroll
    for (int q = 0; q < 4; q++) {
        acc[q][0] = xga[q][0].x; acc[q][1] = xga[q][0].y;
        acc[q][2] = xga[q][1].x; acc[q][3] = xga[q][1].y;
    }
#pragma unroll 4
    for (int k = 0; k < H1; k++) {
        const float* wr = W1HI + k * G1 + 4 * j1;
        float4 w4 = *(const float4*)wr;
        u64 wd0 = pack2(w4.x, w4.x);
        u64 wd1 = pack2(w4.y, w4.y);
        u64 wd2 = pack2(w4.z, w4.z);
        u64 wd3 = pack2(w4.w, w4.w);
        const float* sr = H1r + k * BT + b1;
        ulonglong2 xv0 = *(const ulonglong2*)sr;
        ulonglong2 xv1 = *(const ulonglong2*)(sr + 4);
        u64 xp0 = xv0.x, xp1 = xv0.y, xp2 = xv1.x, xp3 = xv1.y;
        acc[0][0] = fma2(xp0, wd0, acc[0][0]);
        acc[0][1] = fma2(xp1, wd0, acc[0][1]);
        acc[0][2] = fma2(xp2, wd0, acc[0][2]);
        acc[0][3] = fma2(xp3, wd0, acc[0][3]);
        acc[1][0] = fma2(xp0, wd1, acc[1][0]);
        acc[1][1] = fma2(xp1, wd1, acc[1][1]);
        acc[1][2] = fma2(xp2, wd1, acc[1][2]);
        acc[1][3] = fma2(xp3, wd1, acc[1][3]);
        acc[2][0] = fma2(xp0, wd2, acc[2][0]);
        acc[2][1] = fma2(xp1, wd2, acc[2][1]);
        acc[2][2] = fma2(xp2, wd2, acc[2][2]);
        acc[2][3] = fma2(xp3, wd2, acc[2][3]);
        acc[3][0] = fma2(xp0, wd3, acc[3][0]);
        acc[3][1] = fma2(xp1, wd3, acc[3][1]);
        acc[3][2] = fma2(xp2, wd3, acc[3][2]);
        acc[3][3] = fma2(xp3, wd3, acc[3][3]);
    }
    // prefetch XG(tn+1)
    if (tn + 1 < TT) {
#pragma unroll
        for (int q = 0; q < 4; q++) {
            const float* p = xgbase +
                (size_t)((tn + 1) * G1 + 4 * j1 + q) * BT + b1;
            xga[q][0] = *(const ulonglong2*)p;
            xga[q][1] = *(const ulonglong2*)(p + 4);
        }
    }
    float h8[8];
#pragma unroll
    for (int p = 0; p < 4; p++) {
        float2 ai = u2f2(acc[0][p]);
        float2 af = u2f2(acc[1][p]);
        float2 ag = u2f2(acc[2][p]);
        float2 ao = u2f2(acc[3][p]);
#pragma unroll
        for (int m = 0; m < 2; m++) {
            int e = 2 * p + m;
            float iv = sigf(m ? ai.y : ai.x);
            float fv = sigf(m ? af.y : af.x);
            float gv = tanhf_(m ? ag.y : ag.x);
            float ov = sigf(m ? ao.y : ao.x);
            float c = fv * c1[e] + iv * gv;
            c1[e] = c;
            h8[e] = ov * tanhf_(c);
        }
    }
    float4 hv0, hv1;
    hv0.x = h8[0]; hv0.y = h8[1]; hv0.z = h8[2]; hv0.w = h8[3];
    hv1.x = h8[4]; hv1.y = h8[5]; hv1.z = h8[6]; hv1.w = h8[7];
    *(float4*)(H1w + j1 * BT + b1) = hv0;
    *(float4*)(H1w + j1 * BT + b1 + 4) = hv1;
}

extern __shared__ float smemB[];
__global__ __launch_bounds__(NTB, 1) void lstm_phaseB(
    const float* __restrict__ w_hh1,
    const float* __restrict__ w_ih2, const float* __restrict__ w_hh2,
    const float* __restrict__ b_ih2, const float* __restrict__ b_hh2,
    const float* __restrict__ w_ih3, const float* __restrict__ w_hh3,
    const float* __restrict__ b_ih3, const float* __restrict__ b_hh3,
    const float* __restrict__ fc_w, const float* __restrict__ fc_b,
    float* __restrict__ out) {
    const int tid = threadIdx.x;
    const int cta = blockIdx.x;

    float* W1HI = smemB + OFFB_W1HI;
    float* W2XI = smemB + OFFB_W2XI;
    float* W2HI = smemB + OFFB_W2HI;
    float* B2I  = smemB + OFFB_B2I;
    float* W3XI = smemB + OFFB_W3XI;
    float* W3HI = smemB + OFFB_W3HI;
    float* B3I  = smemB + OFFB_B3I;
    float* H1B  = smemB + OFFB_H1;
    float* H2B  = smemB + OFFB_H2;
    float* H3B  = smemB + OFFB_H3;

    // ---- stage weights interleaved [k][4j+q] (non-duplicated) ----
    for (int i = tid; i < G1 * H1; i += NTB) {
        int g = i >> 5, k = i & 31;
        W1HI[k * G1 + 4 * (g & 31) + (g >> 5)] = w_hh1[i];
    }
    for (int i = tid; i < G2 * H1; i += NTB) {
        int g = i >> 5, k = i & 31;
        W2XI[k * G2 + 4 * (g & 15) + (g >> 4)] = w_ih2[i];
    }
    for (int i = tid; i < G2 * H2; i += NTB) {
        int g = i >> 4, k = i & 15;
        W2HI[k * G2 + 4 * (g & 15) + (g >> 4)] = w_hh2[i];
    }
    for (int i = tid; i < G2; i += NTB)
        B2I[4 * (i & 15) + (i >> 4)] = b_ih2[i] + b_hh2[i];
    for (int i = tid; i < G3 * H2; i += NTB) {
        int g = i >> 4, k = i & 15;
        W3XI[k * G3 + 4 * (g & 7) + (g >> 3)] = w_ih3[i];
    }
    for (int i = tid; i < G3 * H3; i += NTB) {
        int g = i >> 3, k = i & 7;
        W3HI[k * G3 + 4 * (g & 7) + (g >> 3)] = w_hh3[i];
    }
    for (int i = tid; i < G3; i += NTB)
        B3I[4 * (i & 7) + (i >> 3)] = b_ih3[i] + b_hh3[i];
    for (int i = tid; i < 2 * H1 * BT; i += NTB) H1B[i] = 0.f;
    for (int i = tid; i < 2 * H2 * BT; i += NTB) H2B[i] = 0.f;
    for (int i = tid; i < 2 * H3 * BT; i += NTB) H3B[i] = 0.f;

    const float* xgbase = g_xg + (size_t)cta * TT * G1 * BT;

    // ---- group A state (warps 0-7) ----
    const int j1 = tid >> 3;            // 0..31 (valid when tid<256)
    const int b1 = (tid & 7) * 8;
    float c1[8] = {0.f, 0.f, 0.f, 0.f, 0.f, 0.f, 0.f, 0.f};
    ulonglong2 xga[4][2];

    // ---- group B state (warps 8-15) ----
    const int tid2 = tid - 256;
    const int j2 = tid2 >> 4;           // 0..15
    const int b2 = (tid2 & 15) * 4;
    const int j3 = tid2 >> 5;           // 0..7
    const int b3l = (tid2 & 31) * 2;
    float c2[4] = {0.f, 0.f, 0.f, 0.f};
    float c3[2] = {0.f, 0.f};

    if (tid < 256) {
#pragma unroll
        for (int q = 0; q < 4; q++) {
            const float* p = xgbase + (size_t)(4 * j1 + q) * BT + b1;
            xga[q][0] = *(const ulonglong2*)p;
            xga[q][1] = *(const ulonglong2*)(p + 4);
        }
    }
    __syncthreads();     // weights + zeroed buffers + xg prefetch visible

    // prologue: A computes h1(0)
    if (tid < 256)
        stage1_step(0, xgbase, W1HI, H1B, xga, c1, j1, b1);
    __syncthreads();

    for (int t = 0; t < TT; ++t) {
        if (tid < 256) {
            // A: compute h1(t+1) while B handles layers 2-3 for t
            if (t + 1 < TT)
                stage1_step(t + 1, xgbase, W1HI, H1B, xga, c1, j1, b1);
        } else {
            const float* H1t = H1B + ((t & 1) << 11);          // h1(t)
            const float* H2r = H2B + (((t + 1) & 1) << 10);    // h2(t-1)
            float* H2w = H2B + ((t & 1) << 10);                // h2(t)
            const float* H3r = H3B + (((t + 1) & 1) << 9);     // h3(t-1)
            float* H3w = H3B + ((t & 1) << 9);                 // h3(t)

            // ---- L2 gates + ew ----
            {
                u64 acc[4][2];
                float4 bv4 = *(const float4*)(B2I + 4 * j2);
                acc[0][0] = pack2(bv4.x, bv4.x); acc[0][1] = acc[0][0];
                acc[1][0] = pack2(bv4.y, bv4.y); acc[1][1] = acc[1][0];
                acc[2][0] = pack2(bv4.z, bv4.z); acc[2][1] = acc[2][0];
                acc[3][0] = pack2(bv4.w, bv4.w); acc[3][1] = acc[3][0];
#pragma unroll 4
                for (int k = 0; k < H1; k++) {
                    const float* wr = W2XI + k * G2 + 4 * j2;
                    float4 w4 = *(const float4*)wr;
                    u64 wd0 = pack2(w4.x, w4.x), wd1 = pack2(w4.y, w4.y);
                    u64 wd2 = pack2(w4.z, w4.z), wd3 = pack2(w4.w, w4.w);
                    ulonglong2 xv = *(const ulonglong2*)(H1t + k * BT + b2);
                    acc[0][0] = fma2(xv.x, wd0, acc[0][0]);
                    acc[0][1] = fma2(xv.y, wd0, acc[0][1]);
                    acc[1][0] = fma2(xv.x, wd1, acc[1][0]);
                    acc[1][1] = fma2(xv.y, wd1, acc[1][1]);
                    acc[2][0] = fma2(xv.x, wd2, acc[2][0]);
                    acc[2][1] = fma2(xv.y, wd2, acc[2][1]);
                    acc[3][0] = fma2(xv.x, wd3, acc[3][0]);
                    acc[3][1] = fma2(xv.y, wd3, acc[3][1]);
                }
#pragma unroll 4
                for (int k = 0; k < H2; k++) {
                    const float* wr = W2HI + k * G2 + 4 * j2;
                    float4 w4 = *(const float4*)wr;
                    u64 wd0 = pack2(w4.x, w4.x), wd1 = pack2(w4.y, w4.y);
                    u64 wd2 = pack2(w4.z, w4.z), wd3 = pack2(w4.w, w4.w);
                    ulonglong2 xv = *(const ulonglong2*)(H2r + k * BT + b2);
                    acc[0][0] = fma2(xv.x, wd0, acc[0][0]);
                    acc[0][1] = fma2(xv.y, wd0, acc[0][1]);
                    acc[1][0] = fma2(xv.x, wd1, acc[1][0]);
                    acc[1][1] = fma2(xv.y, wd1, acc[1][1]);
                    acc[2][0] = fma2(xv.x, wd2, acc[2][0]);
                    acc[2][1] = fma2(xv.y, wd2, acc[2][1]);
                    acc[3][0] = fma2(xv.x, wd3, acc[3][0]);
                    acc[3][1] = fma2(xv.y, wd3, acc[3][1]);
                }
                float h4[4];
#pragma unroll
                for (int p = 0; p < 2; p++) {
                    float2 ai = u2f2(acc[0][p]);
                    float2 af = u2f2(acc[1][p]);
                    float2 ag = u2f2(acc[2][p]);
                    float2 ao = u2f2(acc[3][p]);
#pragma unroll
                    for (int m = 0; m < 2; m++) {
                        int e = 2 * p + m;
                        float iv = sigf(m ? ai.y : ai.x);
                        float fv = sigf(m ? af.y : af.x);
                        float gv = tanhf_(m ? ag.y : ag.x);
                        float ov = sigf(m ? ao.y : ao.x);
                        float c = fv * c2[e] + iv * gv;
                        c2[e] = c;
                        h4[e] = ov * tanhf_(c);
                    }
                }
                float4 hv; hv.x = h4[0]; hv.y = h4[1]; hv.z = h4[2]; hv.w = h4[3];
                *(float4*)(H2w + j2 * BT + b2) = hv;
            }
            asm volatile("bar.sync 1, 256;" ::: "memory");   // B-group only

            // ---- L3 gates + ew (gate-pair f32x2, 2 batch) ----
            {
                u64 aif0 = *(const u64*)(B3I + 4 * j3);
                u64 ago0 = *(const u64*)(B3I + 4 * j3 + 2);
                u64 aif1 = aif0, ago1 = ago0;
#pragma unroll 4
                for (int k = 0; k < H2; k++) {
                    ulonglong2 w = *(const ulonglong2*)(W3XI + k * G3 + 4 * j3);
                    float2 s = *(const float2*)(H2w + k * BT + b3l);
                    u64 s0 = pack2(s.x, s.x), s1 = pack2(s.y, s.y);
                    aif0 = fma2(s0, w.x, aif0);
                    ago0 = fma2(s0, w.y, ago0);
                    aif1 = fma2(s1, w.x, aif1);
                    ago1 = fma2(s1, w.y, ago1);
                }
#pragma unroll
                for (int k = 0; k < H3; k++) {
                    ulonglong2 w = *(const ulonglong2*)(W3HI + k * G3 + 4 * j3);
                    float2 s = *(const float2*)(H3r + k * BT + b3l);
                    u64 s0 = pack2(s.x, s.x), s1 = pack2(s.y, s.y);
                    aif0 = fma2(s0, w.x, aif0);
                    ago0 = fma2(s0, w.y, ago0);
                    aif1 = fma2(s1, w.x, aif1);
                    ago1 = fma2(s1, w.y, ago1);
                }
                float hv[2];
#pragma unroll
                for (int m = 0; m < 2; m++) {
                    float2 vif = u2f2(m ? aif1 : aif0);
                    float2 vgo = u2f2(m ? ago1 : ago0);
                    float iv = sigf(vif.x);
                    float fv = sigf(vif.y);
                    float gv = tanhf_(vgo.x);
                    float ov = sigf(vgo.y);
                    float c = fv * c3[m] + iv * gv;
                    c3[m] = c;
                    hv[m] = ov * tanhf_(c);
                }
                float2 h2s; h2s.x = hv[0]; h2s.y = hv[1];
                *(float2*)(H3w + j3 * BT + b3l) = h2s;
            }
        }
        __syncthreads();
    }

    // final FC: h3(63) in buffer 1
    if (tid < BT) {
        const float* H3f = H3B + 512;
        float acc = fc_b[0];
#pragma unroll
        for (int j = 0; j < H3; j++) acc += fc_w[j] * H3f[j * BT + tid];
        out[cta * BT + tid] = acc;
    }
}

extern "C" void kernel_launch(void* const* d_in, const int* in_sizes, int n_in,
                              void* d_out, int out_size) {
    (void)in_sizes; (void)n_in; (void)out_size;
    const float* x     = (const float*)d_in[0];
    const float* w_ih1 = (const float*)d_in[1];
    const float* w_hh1 = (const float*)d_in[2];
    const float* b_ih1 = (const float*)d_in[3];
    const float* b_hh1 = (const float*)d_in[4];
    const float* w_ih2 = (const float*)d_in[5];
    const float* w_hh2 = (const float*)d_in[6];
    const float* b_ih2 = (const float*)d_in[7];
    const float* b_hh2 = (const float*)d_in[8];
    const float* w_ih3 = (const float*)d_in[9];
    const float* w_hh3 = (const float*)d_in[10];
    const float* b_ih3 = (const float*)d_in[11];
    const float* b_hh3 = (const float*)d_in[12];
    const float* fc_w  = (const float*)d_in[13];
    const float* fc_b  = (const float*)d_in[14];
    float* out = (float*)d_out;

    cudaFuncSetAttribute(lstm_phaseA,
                         cudaFuncAttributeMaxDynamicSharedMemorySize, A_SMEM_BYTES);
    cudaFuncSetAttribute(lstm_phaseB,
                         cudaFuncAttributeMaxDynamicSharedMemorySize, B_SMEM_BYTES);

    dim3 gridA(TT / TPB, NCTA);
    lstm_phaseA<<<gridA, NTA, A_SMEM_BYTES>>>(x, w_ih1, b_ih1, b_hh1);
    lstm_phaseB<<<NCTA, NTB, B_SMEM_BYTES>>>(
        w_hh1, w_ih2, w_hh2, b_ih2, b_hh2,
        w_ih3, w_hh3, b_ih3, b_hh3, fc_w, fc_b, out);
}

// round 8
// speedup vs baseline: 1.2604x; 1.0233x over previous
#include <cuda_runtime.h>

typedef unsigned long long u64;

#define TT    64
#define BATCH 8192
#define DIN   128

#define G1 128
#define G2 64
#define G3 32
#define H1 32
#define H2 16
#define H3 8

// ---------------- phase A (batch tile 64) ----------------
#define BTA  64
#define NCTA_A (BATCH / BTA)
#define TPB 8
#define NTA 256
#define WSTRA 132
#define XSTR 68
#define A_SMEM_FLOATS (DIN * WSTRA + DIN * XSTR)
#define A_SMEM_BYTES  (A_SMEM_FLOATS * 4)

// ---------------- phase B (batch tile 32, 2 CTAs/SM) ----------------
#define BTB  32
#define NCTA_B (BATCH / BTB)
#define NTB 512
#define HP 36                 // padded pitch for h buffers
#define H1SZ (H1 * HP)        // 1152
#define H2SZ (H2 * HP)        // 576
#define H3SZ (H3 * HP)        // 288
#define OFFB_W1HI 0           // [32k][128]
#define OFFB_W2XI 4096        // [32k][64]
#define OFFB_W2HI 6144        // [16k][64]
#define OFFB_B2I  7168        // [64]
#define OFFB_W3XI 7232        // [16k][32]
#define OFFB_W3HI 7744        // [8k][32]
#define OFFB_B3I  8000        // [32]
#define OFFB_H1   8032        // 2 x H1SZ
#define OFFB_H2   (OFFB_H1 + 2 * H1SZ)
#define OFFB_H3   (OFFB_H2 + 2 * H2SZ)
#define B_SMEM_FLOATS (OFFB_H3 + 2 * H3SZ)
#define B_SMEM_BYTES  (B_SMEM_FLOATS * 4)

// 256 MB scratch: XG[ctaA][t][row(4j+q)][bl0..63]
__device__ float g_xg[(size_t)NCTA_A * TT * G1 * BTA];

__device__ __forceinline__ u64 pack2(float a, float b) {
    u64 r;
    asm("mov.b64 %0, {%1, %2};" : "=l"(r) : "f"(a), "f"(b));
    return r;
}
__device__ __forceinline__ u64 fma2(u64 a, u64 b, u64 c) {
    u64 d;
    asm("fma.rn.f32x2 %0, %1, %2, %3;" : "=l"(d) : "l"(a), "l"(b), "l"(c));
    return d;
}
__device__ __forceinline__ float2 u2f2(u64 v) {
    float2 r;
    asm("mov.b64 {%0, %1}, %2;" : "=f"(r.x), "=f"(r.y) : "l"(v));
    return r;
}
__device__ __forceinline__ float sigf(float v) {
    return __fdividef(1.f, 1.f + __expf(-v));
}
__device__ __forceinline__ float tanhf_(float v) {
    return 1.f - __fdividef(2.f, __expf(2.f * v) + 1.f);
}

// ======================= PHASE A =======================
extern __shared__ float smemA[];

__device__ __forceinline__ void compute_halfA(const float* __restrict__ WS,
                                              const float* __restrict__ XT,
                                              u64 (&acc)[8][2],
                                              int g0, int b0l, int h) {
#pragma unroll 2
    for (int kk = 0; kk < 64; kk++) {
        int k = h * 64 + kk;
        const float* wr = WS + k * WSTRA + g0;
        float4 wa = *(const float4*)wr;
        float4 wb = *(const float4*)(wr + 4);
        ulonglong2 xv = *(const ulonglong2*)(XT + k * XSTR + b0l);
        u64 wd[8];
        wd[0] = pack2(wa.x, wa.x); wd[1] = pack2(wa.y, wa.y);
        wd[2] = pack2(wa.z, wa.z); wd[3] = pack2(wa.w, wa.w);
        wd[4] = pack2(wb.x, wb.x); wd[5] = pack2(wb.y, wb.y);
        wd[6] = pack2(wb.z, wb.z); wd[7] = pack2(wb.w, wb.w);
#pragma unroll
        for (int i = 0; i < 8; i++) {
            acc[i][0] = fma2(xv.x, wd[i], acc[i][0]);
            acc[i][1] = fma2(xv.y, wd[i], acc[i][1]);
        }
    }
}

__global__ __launch_bounds__(NTA, 2) void lstm_phaseA(
    const float* __restrict__ x,
    const float* __restrict__ w_ih1,
    const float* __restrict__ b_ih1,
    const float* __restrict__ b_hh1) {
    float* WS = smemA;
    float* XT = smemA + DIN * WSTRA;
    const int tid = threadIdx.x;
    const int wrp = tid >> 5, ln = tid & 31;
    const int tg  = blockIdx.x;
    const int cta = blockIdx.y;
    const int b0g = cta * BTA;
    const int t0  = tg * TPB;

    // stage weights gate-interleaved: WS[k][4j+q] <- w_ih1[q*32+j][k]
    for (int idx = tid; idx < G1 * DIN; idx += NTA) {
        int rr = idx >> 7, k = idx & 127;
        int g = ((rr & 3) << 5) + (rr >> 2);
        WS[k * WSTRA + rr] = w_ih1[g * DIN + k];
    }
    const int g0 = (tid >> 4) * 8;
    const int b0l = (tid & 15) * 4;
    u64 bd[8];
#pragma unroll
    for (int i = 0; i < 8; i++) {
        int rr = g0 + i;
        int g = ((rr & 3) << 5) + (rr >> 2);
        float bv = b_ih1[g] + b_hh1[g];
        bd[i] = pack2(bv, bv);
    }

    // half-tile x prefetch registers (16 floats each)
    float xa[16], xb[16];
    // load half h of timestep t into dst
#define LOADX_H(t, h, dst)                                                  \
    {                                                                       \
        _Pragma("unroll") for (int r2 = 0; r2 < 8; r2++) {                  \
            const float* xrow = x +                                         \
                ((size_t)(b0g + wrp * 8 + r2) * TT + (t)) * DIN;            \
            _Pragma("unroll") for (int i = 0; i < 2; i++)                   \
                dst[r2 * 2 + i] = xrow[((h) * 2 + i) * 32 + ln];            \
        }                                                                   \
    }
#define STOREX_H(h, src)                                                    \
    {                                                                       \
        _Pragma("unroll") for (int r2 = 0; r2 < 8; r2++)                    \
            _Pragma("unroll") for (int i = 0; i < 2; i++)                   \
                XT[(((h) * 2 + i) * 32 + ln) * XSTR + wrp * 8 + r2] =       \
                    src[r2 * 2 + i];                                        \
    }

    LOADX_H(t0, 0, xa);
    __syncthreads();          // weights staged
    STOREX_H(0, xa);
    LOADX_H(t0, 1, xb);
    __syncthreads();          // XT half0(t0) ready

    for (int tt = 0; tt < TPB; tt++) {
        const int t = t0 + tt;

        STOREX_H(1, xb);                          // t half1 -> XT rows 64..127
        u64 acc[8][2];
#pragma unroll
        for (int i = 0; i < 8; i++) { acc[i][0] = bd[i]; acc[i][1] = bd[i]; }
        compute_halfA(WS, XT, acc, g0, b0l, 0);   // reads XT rows 0..63
        if (tt + 1 < TPB) LOADX_H(t + 1, 0, xa);
        __syncthreads();      // half1 staged; all reads of half0 done

        if (tt + 1 < TPB) { STOREX_H(0, xa); }    // t+1 half0 -> XT rows 0..63
        compute_halfA(WS, XT, acc, g0, b0l, 1);   // reads XT rows 64..127

        float* xgout = g_xg + ((size_t)(cta * TT + t) * G1) * BTA;
#pragma unroll
        for (int i = 0; i < 8; i++) {
            ulonglong2 v;
            v.x = acc[i][0]; v.y = acc[i][1];
            *(ulonglong2*)(xgout + (size_t)(g0 + i) * BTA + b0l) = v;
        }
        if (tt + 1 < TPB) LOADX_H(t + 1, 1, xb);
        __syncthreads();      // half0(t+1) staged; reads of half1 done
    }
}

// ======================= PHASE B (BT=32, pipelined, 2 CTAs/SM) =======================
// Warps 0-7 (A): layer-1 recurrence, one step ahead.  Warps 8-15 (B): layers 2+3.

__device__ __forceinline__ void stage1_step(
    int tn, const float* __restrict__ xgbase, const float* __restrict__ W1HI,
    float* __restrict__ H1B, ulonglong2 (&xga)[4], float (&c1)[4],
    int j1, int b1) {
    const float* H1r = H1B + ((tn + 1) & 1) * H1SZ;   // h1(tn-1)
    float* H1w = H1B + (tn & 1) * H1SZ;               // h1(tn)

    u64 acc[4][2];
#pragma unroll
    for (int q = 0; q < 4; q++) { acc[q][0] = xga[q].x; acc[q][1] = xga[q].y; }
#pragma unroll 4
    for (int k = 0; k < H1; k++) {
        const float* wr = W1HI + k * G1 + 4 * j1;
        float4 w4 = *(const float4*)wr;
        u64 wd0 = pack2(w4.x, w4.x);
        u64 wd1 = pack2(w4.y, w4.y);
        u64 wd2 = pack2(w4.z, w4.z);
        u64 wd3 = pack2(w4.w, w4.w);
        ulonglong2 xv = *(const ulonglong2*)(H1r + k * HP + b1);
        acc[0][0] = fma2(xv.x, wd0, acc[0][0]);
        acc[0][1] = fma2(xv.y, wd0, acc[0][1]);
        acc[1][0] = fma2(xv.x, wd1, acc[1][0]);
        acc[1][1] = fma2(xv.y, wd1, acc[1][1]);
        acc[2][0] = fma2(xv.x, wd2, acc[2][0]);
        acc[2][1] = fma2(xv.y, wd2, acc[2][1]);
        acc[3][0] = fma2(xv.x, wd3, acc[3][0]);
        acc[3][1] = fma2(xv.y, wd3, acc[3][1]);
    }
    if (tn + 1 < TT) {
#pragma unroll
        for (int q = 0; q < 4; q++)
            xga[q] = *(const ulonglong2*)(xgbase +
                (size_t)((tn + 1) * G1 + 4 * j1 + q) * BTA + b1);
    }
    float h4[4];
#pragma unroll
    for (int p = 0; p < 2; p++) {
        float2 ai = u2f2(acc[0][p]);
        float2 af = u2f2(acc[1][p]);
        float2 ag = u2f2(acc[2][p]);
        float2 ao = u2f2(acc[3][p]);
#pragma unroll
        for (int m = 0; m < 2; m++) {
            int e = 2 * p + m;
            float iv = sigf(m ? ai.y : ai.x);
            float fv = sigf(m ? af.y : af.x);
            float gv = tanhf_(m ? ag.y : ag.x);
            float ov = sigf(m ? ao.y : ao.x);
            float c = fv * c1[e] + iv * gv;
            c1[e] = c;
            h4[e] = ov * tanhf_(c);
        }
    }
    float4 hv; hv.x = h4[0]; hv.y = h4[1]; hv.z = h4[2]; hv.w = h4[3];
    *(float4*)(H1w + j1 * HP + b1) = hv;
}

extern __shared__ float smemB[];
__global__ __launch_bounds__(NTB, 2) void lstm_phaseB(
    const float* __restrict__ w_hh1,
    const float* __restrict__ w_ih2, const float* __restrict__ w_hh2,
    const float* __restrict__ b_ih2, const float* __restrict__ b_hh2,
    const float* __restrict__ w_ih3, const float* __restrict__ w_hh3,
    const float* __restrict__ b_ih3, const float* __restrict__ b_hh3,
    const float* __restrict__ fc_w, const float* __restrict__ fc_b,
    float* __restrict__ out) {
    const int tid = threadIdx.x;
    const int cta = blockIdx.x;      // 0..255, 32 batch each

    float* W1HI = smemB + OFFB_W1HI;
    float* W2XI = smemB + OFFB_W2XI;
    float* W2HI = smemB + OFFB_W2HI;
    float* B2I  = smemB + OFFB_B2I;
    float* W3XI = smemB + OFFB_W3XI;
    float* W3HI = smemB + OFFB_W3HI;
    float* B3I  = smemB + OFFB_B3I;
    float* H1B  = smemB + OFFB_H1;
    float* H2B  = smemB + OFFB_H2;
    float* H3B  = smemB + OFFB_H3;

    // ---- stage weights interleaved [k][4j+q] ----
    for (int i = tid; i < G1 * H1; i += NTB) {
        int g = i >> 5, k = i & 31;
        W1HI[k * G1 + 4 * (g & 31) + (g >> 5)] = w_hh1[i];
    }
    for (int i = tid; i < G2 * H1; i += NTB) {
        int g = i >> 5, k = i & 31;
        W2XI[k * G2 + 4 * (g & 15) + (g >> 4)] = w_ih2[i];
    }
    for (int i = tid; i < G2 * H2; i += NTB) {
        int g = i >> 4, k = i & 15;
        W2HI[k * G2 + 4 * (g & 15) + (g >> 4)] = w_hh2[i];
    }
    for (int i = tid; i < G2; i += NTB)
        B2I[4 * (i & 15) + (i >> 4)] = b_ih2[i] + b_hh2[i];
    for (int i = tid; i < G3 * H2; i += NTB) {
        int g = i >> 4, k = i & 15;
        W3XI[k * G3 + 4 * (g & 7) + (g >> 3)] = w_ih3[i];
    }
    for (int i = tid; i < G3 * H3; i += NTB) {
        int g = i >> 3, k = i & 7;
        W3HI[k * G3 + 4 * (g & 7) + (g >> 3)] = w_hh3[i];
    }
    for (int i = tid; i < G3; i += NTB)
        B3I[4 * (i & 7) + (i >> 3)] = b_ih3[i] + b_hh3[i];
    for (int i = tid; i < 2 * H1SZ; i += NTB) H1B[i] = 0.f;
    for (int i = tid; i < 2 * H2SZ; i += NTB) H2B[i] = 0.f;
    for (int i = tid; i < 2 * H3SZ; i += NTB) H3B[i] = 0.f;

    // XG base for this 32-batch slice (phase A wrote 64-wide tiles)
    const float* xgbase = g_xg +
        (size_t)(cta >> 1) * TT * G1 * BTA + (cta & 1) * BTB;

    // ---- group A (warps 0-7): L1, 1 j x 4 batch per thread ----
    const int j1 = tid >> 3;             // 0..31
    const int b1 = (tid & 7) * 4;        // 0..28
    float c1[4] = {0.f, 0.f, 0.f, 0.f};
    ulonglong2 xga[4];

    // ---- group B (warps 8-15) ----
    const int tid2 = tid - 256;
    const int j2 = tid2 >> 4;            // 0..15
    const int b2 = (tid2 & 15) * 2;      // 0..30
    const int j3 = tid2 >> 5;            // 0..7
    const int b3 = tid2 & 31;            // 0..31
    float c2[2] = {0.f, 0.f};
    float c3 = 0.f;

    if (tid < 256) {
#pragma unroll
        for (int q = 0; q < 4; q++)
            xga[q] = *(const ulonglong2*)(xgbase +
                (size_t)(4 * j1 + q) * BTA + b1);
    }
    __syncthreads();

    // prologue: h1(0)
    if (tid < 256)
        stage1_step(0, xgbase, W1HI, H1B, xga, c1, j1, b1);
    __syncthreads();

    for (int t = 0; t < TT; ++t) {
        if (tid < 256) {
            if (t + 1 < TT)
                stage1_step(t + 1, xgbase, W1HI, H1B, xga, c1, j1, b1);
        } else {
            const float* H1t = H1B + (t & 1) * H1SZ;          // h1(t)
            const float* H2r = H2B + ((t + 1) & 1) * H2SZ;    // h2(t-1)
            float* H2w = H2B + (t & 1) * H2SZ;                // h2(t)
            const float* H3r = H3B + ((t + 1) & 1) * H3SZ;    // h3(t-1)
            float* H3w = H3B + (t & 1) * H3SZ;                // h3(t)

            // ---- L2 gates + ew ----
            {
                u64 acc[4];
                float4 bv4 = *(const float4*)(B2I + 4 * j2);
                acc[0] = pack2(bv4.x, bv4.x);
                acc[1] = pack2(bv4.y, bv4.y);
                acc[2] = pack2(bv4.z, bv4.z);
                acc[3] = pack2(bv4.w, bv4.w);
#pragma unroll 4
                for (int k = 0; k < H1; k++) {
                    const float* wr = W2XI + k * G2 + 4 * j2;
                    float4 w4 = *(const float4*)wr;
                    u64 xv = *(const u64*)(H1t + k * HP + b2);
                    acc[0] = fma2(xv, pack2(w4.x, w4.x), acc[0]);
                    acc[1] = fma2(xv, pack2(w4.y, w4.y), acc[1]);
                    acc[2] = fma2(xv, pack2(w4.z, w4.z), acc[2]);
                    acc[3] = fma2(xv, pack2(w4.w, w4.w), acc[3]);
                }
#pragma unroll 4
                for (int k = 0; k < H2; k++) {
                    const float* wr = W2HI + k * G2 + 4 * j2;
                    float4 w4 = *(const float4*)wr;
                    u64 xv = *(const u64*)(H2r + k * HP + b2);
                    acc[0] = fma2(xv, pack2(w4.x, w4.x), acc[0]);
                    acc[1] = fma2(xv, pack2(w4.y, w4.y), acc[1]);
                    acc[2] = fma2(xv, pack2(w4.z, w4.z), acc[2]);
                    acc[3] = fma2(xv, pack2(w4.w, w4.w), acc[3]);
                }
                float2 ai = u2f2(acc[0]);
                float2 af = u2f2(acc[1]);
                float2 ag = u2f2(acc[2]);
                float2 ao = u2f2(acc[3]);
                float h2v[2];
#pragma unroll
                for (int m = 0; m < 2; m++) {
                    float iv = sigf(m ? ai.y : ai.x);
                    float fv = sigf(m ? af.y : af.x);
                    float gv = tanhf_(m ? ag.y : ag.x);
                    float ov = sigf(m ? ao.y : ao.x);
                    float c = fv * c2[m] + iv * gv;
                    c2[m] = c;
                    h2v[m] = ov * tanhf_(c);
                }
                float2 hv; hv.x = h2v[0]; hv.y = h2v[1];
                *(float2*)(H2w + j2 * HP + b2) = hv;
            }
            asm volatile("bar.sync 1, 256;" ::: "memory");   // B-group only

            // ---- L3 gates + ew (gate-pair f32x2, 1 batch) ----
            {
                u64 aif = *(const u64*)(B3I + 4 * j3);
                u64 ago = *(const u64*)(B3I + 4 * j3 + 2);
#pragma unroll 4
                for (int k = 0; k < H2; k++) {
                    ulonglong2 w = *(const ulonglong2*)(W3XI + k * G3 + 4 * j3);
                    float s = H2w[k * HP + b3];
                    u64 ss = pack2(s, s);
                    aif = fma2(ss, w.x, aif);
                    ago = fma2(ss, w.y, ago);
                }
#pragma unroll
                for (int k = 0; k < H3; k++) {
                    ulonglong2 w = *(const ulonglong2*)(W3HI + k * G3 + 4 * j3);
                    float s = H3r[k * HP + b3];
                    u64 ss = pack2(s, s);
                    aif = fma2(ss, w.x, aif);
                    ago = fma2(ss, w.y, ago);
                }
                float2 vif = u2f2(aif), vgo = u2f2(ago);
                float iv = sigf(vif.x);
                float fv = sigf(vif.y);
                float gv = tanhf_(vgo.x);
                float ov = sigf(vgo.y);
                float c = fv * c3 + iv * gv;
                c3 = c;
                H3w[j3 * HP + b3] = ov * tanhf_(c);
            }
        }
        __syncthreads();
    }

    // final FC: h3(63) in buffer 1
    if (tid < BTB) {
        const float* H3f = H3B + H3SZ;
        float acc = fc_b[0];
#pragma unroll
        for (int j = 0; j < H3; j++) acc += fc_w[j] * H3f[j * HP + tid];
        out[cta * BTB + tid] = acc;
    }
}

extern "C" void kernel_launch(void* const* d_in, const int* in_sizes, int n_in,
                              void* d_out, int out_size) {
    (void)in_sizes; (void)n_in; (void)out_size;
    const float* x     = (const float*)d_in[0];
    const float* w_ih1 = (const float*)d_in[1];
    const float* w_hh1 = (const float*)d_in[2];
    const float* b_ih1 = (const float*)d_in[3];
    const float* b_hh1 = (const float*)d_in[4];
    const float* w_ih2 = (const float*)d_in[5];
    const float* w_hh2 = (const float*)d_in[6];
    const float* b_ih2 = (const float*)d_in[7];
    const float* b_hh2 = (const float*)d_in[8];
    const float* w_ih3 = (const float*)d_in[9];
    const float* w_hh3 = (const float*)d_in[10];
    const float* b_ih3 = (const float*)d_in[11];
    const float* b_hh3 = (const float*)d_in[12];
    const float* fc_w  = (const float*)d_in[13];
    const float* fc_b  = (const float*)d_in[14];
    float* out = (float*)d_out;

    cudaFuncSetAttribute(lstm_phaseA,
                         cudaFuncAttributeMaxDynamicSharedMemorySize, A_SMEM_BYTES);
    cudaFuncSetAttribute(lstm_phaseB,
                         cudaFuncAttributeMaxDynamicSharedMemorySize, B_SMEM_BYTES);

    dim3 gridA(TT / TPB, NCTA_A);
    lstm_phaseA<<<gridA, NTA, A_SMEM_BYTES>>>(x, w_ih1, b_ih1, b_hh1);
    lstm_phaseB<<<NCTA_B, NTB, B_SMEM_BYTES>>>(
        w_hh1, w_ih2, w_hh2, b_ih2, b_hh2,
        w_ih3, w_hh3, b_ih3, b_hh3, fc_w, fc_b, out);
}

// round 10
// speedup vs baseline: 1.3430x; 1.0656x over previous
#include <cuda_runtime.h>
#include <cuda_bf16.h>
#include <cstdint>

typedef unsigned long long u64;

#define TT    64
#define BATCH 8192
#define DIN   128

#define G1 128
#define G2 64
#define G3 32
#define H1 32
#define H2 16
#define H3 8

// ---------------- phase A (mma.sync bf16 split GEMM) ----------------
#define NTM_A 256
#define NTILES ((BATCH * TT) / 128)    // 4096 tiles of 128 rows
#define TPB_A 8
#define NBLK_A (NTILES / TPB_A)        // 512 CTAs
#define PW 68                          // smem pitch in 32-bit words (136 bf16)
#define XH_OFF 0
#define XL_OFF 34816
#define WH_OFF 69632
#define WL_OFF 104448
#define A_SMEM_BYTES 139264            // 136 KB -> 1 CTA/SM

// ---------------- phase B (recurrent, BT=32, warp-specialized) ----------------
#define BTB  32
#define NCTA_B (BATCH / BTB)
#define NTB 512
#define HP 36
#define H1SZ (H1 * HP)
#define H2SZ (H2 * HP)
#define H3SZ (H3 * HP)
#define OFFB_W1HI 0
#define OFFB_W2XI 4096
#define OFFB_W2HI 6144
#define OFFB_B2I  7168
#define OFFB_W3XI 7232
#define OFFB_W3HI 7744
#define OFFB_B3I  8000
#define OFFB_H1   8032
#define OFFB_H2   (OFFB_H1 + 2 * H1SZ)
#define OFFB_H3   (OFFB_H2 + 2 * H2SZ)
#define B_SMEM_FLOATS (OFFB_H3 + 2 * H3SZ)
#define B_SMEM_BYTES  (B_SMEM_FLOATS * 4)

// 256 MB scratch: XG[r = b*64 + t][n = 4j+q]  (row-major, bias folded in)
__device__ float g_xg[(size_t)BATCH * TT * G1];

// ======================= common helpers =======================
__device__ __forceinline__ u64 pack2(float a, float b) {
    u64 r;
    asm("mov.b64 %0, {%1, %2};" : "=l"(r) : "f"(a), "f"(b));
    return r;
}
__device__ __forceinline__ u64 fma2(u64 a, u64 b, u64 c) {
    u64 d;
    asm("fma.rn.f32x2 %0, %1, %2, %3;" : "=l"(d) : "l"(a), "l"(b), "l"(c));
    return d;
}
__device__ __forceinline__ float2 u2f2(u64 v) {
    float2 r;
    asm("mov.b64 {%0, %1}, %2;" : "=f"(r.x), "=f"(r.y) : "l"(v));
    return r;
}
__device__ __forceinline__ float sigf(float v) {
    return __fdividef(1.f, 1.f + __expf(-v));
}
__device__ __forceinline__ float tanhf_(float v) {
    return 1.f - __fdividef(2.f, __expf(2.f * v) + 1.f);
}

// mma.sync m16n8k16 row.col bf16 -> f32 accumulate in place
__device__ __forceinline__ void mma_bf16(float (&d)[4],
                                         uint32_t a0, uint32_t a1,
                                         uint32_t a2, uint32_t a3,
                                         uint32_t b0, uint32_t b1) {
    asm volatile(
        "mma.sync.aligned.m16n8k16.row.col.f32.bf16.bf16.f32 "
        "{%0,%1,%2,%3}, {%4,%5,%6,%7}, {%8,%9}, {%0,%1,%2,%3};"
        : "+f"(d[0]), "+f"(d[1]), "+f"(d[2]), "+f"(d[3])
        : "r"(a0), "r"(a1), "r"(a2), "r"(a3), "r"(b0), "r"(b1));
}

// convert one 64-float half-row into hi/lo bf16x2 words
__device__ __forceinline__ void stage_row(const float* __restrict__ src,
                                          uint32_t* __restrict__ H,
                                          uint32_t* __restrict__ L) {
#pragma unroll
    for (int i = 0; i < 16; i++) {
        float4 v = ((const float4*)src)[i];
        __nv_bfloat162 h0 = __float22bfloat162_rn(make_float2(v.x, v.y));
        float2 f0 = __bfloat1622float2(h0);
        __nv_bfloat162 l0 = __float22bfloat162_rn(make_float2(v.x - f0.x, v.y - f0.y));
        __nv_bfloat162 h1 = __float22bfloat162_rn(make_float2(v.z, v.w));
        float2 f1 = __bfloat1622float2(h1);
        __nv_bfloat162 l1 = __float22bfloat162_rn(make_float2(v.z - f1.x, v.w - f1.y));
        H[2 * i]     = *(uint32_t*)&h0;
        H[2 * i + 1] = *(uint32_t*)&h1;
        L[2 * i]     = *(uint32_t*)&l0;
        L[2 * i + 1] = *(uint32_t*)&l1;
    }
}

// ======================= PHASE A (HMMA) =======================
// XG[r][4j+q] = sum_k x[r][k] * w_ih1[q*32+j][k] + b1[q*32+j]
extern __shared__ char smA[];
__global__ __launch_bounds__(NTM_A) void lstm_phaseA_mma(
    const float* __restrict__ x,
    const float* __restrict__ w_ih1,
    const float* __restrict__ b_ih1,
    const float* __restrict__ b_hh1) {
    uint32_t* XH = (uint32_t*)(smA + XH_OFF);
    uint32_t* XL = (uint32_t*)(smA + XL_OFF);
    uint32_t* WH = (uint32_t*)(smA + WH_OFF);
    uint32_t* WL = (uint32_t*)(smA + WL_OFF);

    const int tid = threadIdx.x;
    const int wid = tid >> 5, lid = tid & 31;
    const int g = lid >> 2, tig = lid & 3;
    const int m0w = (wid & 3) * 32;      // warp M offset
    const int n0w = (wid >> 2) * 64;     // warp N offset

    // bias for this thread's D columns (n, n+1) per n-frag
    float2 biasp[8];
#pragma unroll
    for (int nf = 0; nf < 8; nf++) {
        int n = n0w + nf * 8 + tig * 2;
        int ga = ((n & 3) << 5) + (n >> 2);
        int gb = (((n + 1) & 3) << 5) + ((n + 1) >> 2);
        biasp[nf].x = b_ih1[ga] + b_hh1[ga];
        biasp[nf].y = b_ih1[gb] + b_hh1[gb];
    }

    // stage W hi/lo once: row n of W^T = w_ih1 row g(n)
    {
        int row = tid >> 1, c0 = (tid & 1) * 64;
        int gw = ((row & 3) << 5) + (row >> 2);
        stage_row(w_ih1 + (size_t)gw * DIN + c0,
                  WH + row * PW + (c0 >> 1), WL + row * PW + (c0 >> 1));
    }

    for (int tt = 0; tt < TPB_A; tt++) {
        const size_t r0 = ((size_t)blockIdx.x * TPB_A + tt) * 128;
        {
            int row = tid >> 1, c0 = (tid & 1) * 64;
            stage_row(x + (r0 + row) * DIN + c0,
                      XH + row * PW + (c0 >> 1), XL + row * PW + (c0 >> 1));
        }
        __syncthreads();   // W (first iter) + X staged

        float acc[2][8][4];
#pragma unroll
        for (int mi = 0; mi < 2; mi++)
#pragma unroll
            for (int nf = 0; nf < 8; nf++) {
                acc[mi][nf][0] = biasp[nf].x;
                acc[mi][nf][1] = biasp[nf].y;
                acc[mi][nf][2] = biasp[nf].x;
                acc[mi][nf][3] = biasp[nf].y;
            }

#pragma unroll
        for (int ks = 0; ks < 8; ks++) {
            uint32_t ah[2][4], al[2][4];
#pragma unroll
            for (int mi = 0; mi < 2; mi++) {
                int base = (m0w + mi * 16 + g) * PW + tig + ks * 8;
                ah[mi][0] = XH[base];
                ah[mi][1] = XH[base + 8 * PW];
                ah[mi][2] = XH[base + 4];
                ah[mi][3] = XH[base + 8 * PW + 4];
                al[mi][0] = XL[base];
                al[mi][1] = XL[base + 8 * PW];
                al[mi][2] = XL[base + 4];
                al[mi][3] = XL[base + 8 * PW + 4];
            }
#pragma unroll
            for (int nf = 0; nf < 8; nf++) {
                int wb = (n0w + nf * 8 + g) * PW + tig + ks * 8;
                uint32_t bh0 = WH[wb], bh1 = WH[wb + 4];
                uint32_t bl0 = WL[wb], bl1 = WL[wb + 4];
#pragma unroll
                for (int mi = 0; mi < 2; mi++) {
                    mma_bf16(acc[mi][nf], ah[mi][0], ah[mi][1], ah[mi][2], ah[mi][3], bh0, bh1);
                    mma_bf16(acc[mi][nf], ah[mi][0], ah[mi][1], ah[mi][2], ah[mi][3], bl0, bl1);
                    mma_bf16(acc[mi][nf], al[mi][0], al[mi][1], al[mi][2], al[mi][3], bh0, bh1);
                }
            }
        }

        // epilogue: D frags straight to row-major XG
#pragma unroll
        for (int mi = 0; mi < 2; mi++) {
            size_t row = r0 + m0w + mi * 16 + g;
#pragma unroll
            for (int nf = 0; nf < 8; nf++) {
                int col = n0w + nf * 8 + tig * 2;
                float2 v0; v0.x = acc[mi][nf][0]; v0.y = acc[mi][nf][1];
                float2 v1; v1.x = acc[mi][nf][2]; v1.y = acc[mi][nf][3];
                *(float2*)(g_xg + row * G1 + col) = v0;
                *(float2*)(g_xg + (row + 8) * G1 + col) = v1;
            }
        }
        __syncthreads();   // before restaging X
    }
}

// ======================= PHASE B =======================
__device__ __forceinline__ void stage1_step(
    int tn, int bg0, const float* __restrict__ W1HI,
    float* __restrict__ H1B, float4 (&xg)[4], float (&c1)[4],
    int j1, int b1) {
    const float* H1r = H1B + ((tn + 1) & 1) * H1SZ;
    float* H1w = H1B + (tn & 1) * H1SZ;

    const float* x0 = (const float*)&xg[0];
    const float* x1 = (const float*)&xg[1];
    const float* x2 = (const float*)&xg[2];
    const float* x3 = (const float*)&xg[3];
    u64 acc[4][2];
#pragma unroll
    for (int q = 0; q < 4; q++) {
        acc[q][0] = pack2(x0[q], x1[q]);
        acc[q][1] = pack2(x2[q], x3[q]);
    }
#pragma unroll 4
    for (int k = 0; k < H1; k++) {
        const float* wr = W1HI + k * G1 + 4 * j1;
        float4 w4 = *(const float4*)wr;
        u64 wd0 = pack2(w4.x, w4.x);
        u64 wd1 = pack2(w4.y, w4.y);
        u64 wd2 = pack2(w4.z, w4.z);
        u64 wd3 = pack2(w4.w, w4.w);
        ulonglong2 xv = *(const ulonglong2*)(H1r + k * HP + b1);
        acc[0][0] = fma2(xv.x, wd0, acc[0][0]);
        acc[0][1] = fma2(xv.y, wd0, acc[0][1]);
        acc[1][0] = fma2(xv.x, wd1, acc[1][0]);
        acc[1][1] = fma2(xv.y, wd1, acc[1][1]);
        acc[2][0] = fma2(xv.x, wd2, acc[2][0]);
        acc[2][1] = fma2(xv.y, wd2, acc[2][1]);
        acc[3][0] = fma2(xv.x, wd3, acc[3][0]);
        acc[3][1] = fma2(xv.y, wd3, acc[3][1]);
    }
    if (tn + 1 < TT) {
#pragma unroll
        for (int i = 0; i < 4; i++)
            xg[i] = *(const float4*)(g_xg +
                ((size_t)(bg0 + i) * TT + tn + 1) * G1 + 4 * j1);
    }
    float h4[4];
#pragma unroll
    for (int p = 0; p < 2; p++) {
        float2 ai = u2f2(acc[0][p]);
        float2 af = u2f2(acc[1][p]);
        float2 ag = u2f2(acc[2][p]);
        float2 ao = u2f2(acc[3][p]);
#pragma unroll
        for (int m = 0; m < 2; m++) {
            int e = 2 * p + m;
            float iv = sigf(m ? ai.y : ai.x);
            float fv = sigf(m ? af.y : af.x);
            float gv = tanhf_(m ? ag.y : ag.x);
            float ov = sigf(m ? ao.y : ao.x);
            float c = fv * c1[e] + iv * gv;
            c1[e] = c;
            h4[e] = ov * tanhf_(c);
        }
    }
    float4 hv; hv.x = h4[0]; hv.y = h4[1]; hv.z = h4[2]; hv.w = h4[3];
    *(float4*)(H1w + j1 * HP + b1) = hv;
}

extern __shared__ float smemB[];
__global__ __launch_bounds__(NTB, 2) void lstm_phaseB(
    const float* __restrict__ w_hh1,
    const float* __restrict__ w_ih2, const float* __restrict__ w_hh2,
    const float* __restrict__ b_ih2, const float* __restrict__ b_hh2,
    const float* __restrict__ w_ih3, const float* __restrict__ w_hh3,
    const float* __restrict__ b_ih3, const float* __restrict__ b_hh3,
    const float* __restrict__ fc_w, const float* __restrict__ fc_b,
    float* __restrict__ out) {
    const int tid = threadIdx.x;
    const int cta = blockIdx.x;

    float* W1HI = smemB + OFFB_W1HI;
    float* W2XI = smemB + OFFB_W2XI;
    float* W2HI = smemB + OFFB_W2HI;
    float* B2I  = smemB + OFFB_B2I;
    float* W3XI = smemB + OFFB_W3XI;
    float* W3HI = smemB + OFFB_W3HI;
    float* B3I  = smemB + OFFB_B3I;
    float* H1B  = smemB + OFFB_H1;
    float* H2B  = smemB + OFFB_H2;
    float* H3B  = smemB + OFFB_H3;

    for (int i = tid; i < G1 * H1; i += NTB) {
        int g = i >> 5, k = i & 31;
        W1HI[k * G1 + 4 * (g & 31) + (g >> 5)] = w_hh1[i];
    }
    for (int i = tid; i < G2 * H1; i += NTB) {
        int g = i >> 5, k = i & 31;
        W2XI[k * G2 + 4 * (g & 15) + (g >> 4)] = w_ih2[i];
    }
    for (int i = tid; i < G2 * H2; i += NTB) {
        int g = i >> 4, k = i & 15;
        W2HI[k * G2 + 4 * (g & 15) + (g >> 4)] = w_hh2[i];
    }
    for (int i = tid; i < G2; i += NTB)
        B2I[4 * (i & 15) + (i >> 4)] = b_ih2[i] + b_hh2[i];
    for (int i = tid; i < G3 * H2; i += NTB) {
        int g = i >> 4, k = i & 15;
        W3XI[k * G3 + 4 * (g & 7) + (g >> 3)] = w_ih3[i];
    }
    for (int i = tid; i < G3 * H3; i += NTB) {
        int g = i >> 3, k = i & 7;
        W3HI[k * G3 + 4 * (g & 7) + (g >> 3)] = w_hh3[i];
    }
    for (int i = tid; i < G3; i += NTB)
        B3I[4 * (i & 7) + (i >> 3)] = b_ih3[i] + b_hh3[i];
    for (int i = tid; i < 2 * H1SZ; i += NTB) H1B[i] = 0.f;
    for (int i = tid; i < 2 * H2SZ; i += NTB) H2B[i] = 0.f;
    for (int i = tid; i < 2 * H3SZ; i += NTB) H3B[i] = 0.f;

    // group A (warps 0-7): L1, 1 j x 4 batch
    const int j1 = tid >> 3;
    const int b1 = (tid & 7) * 4;
    const int bg0 = cta * BTB + b1;
    float c1[4] = {0.f, 0.f, 0.f, 0.f};
    float4 xg[4];

    // group B (warps 8-15)
    const int tid2 = tid - 256;
    const int j2 = tid2 >> 4;
    const int b2 = (tid2 & 15) * 2;
    const int j3 = tid2 >> 5;
    const int b3 = tid2 & 31;
    float c2[2] = {0.f, 0.f};
    float c3 = 0.f;

    if (tid < 256) {
#pragma unroll
        for (int i = 0; i < 4; i++)
            xg[i] = *(const float4*)(g_xg + (size_t)(bg0 + i) * TT * G1 + 4 * j1);
    }
    __syncthreads();

    if (tid < 256)
        stage1_step(0, bg0, W1HI, H1B, xg, c1, j1, b1);
    __syncthreads();

    for (int t = 0; t < TT; ++t) {
        if (tid < 256) {
            if (t + 1 < TT)
                stage1_step(t + 1, bg0, W1HI, H1B, xg, c1, j1, b1);
        } else {
            const float* H1t = H1B + (t & 1) * H1SZ;
            const float* H2r = H2B + ((t + 1) & 1) * H2SZ;
            float* H2w = H2B + (t & 1) * H2SZ;
            const float* H3r = H3B + ((t + 1) & 1) * H3SZ;
            float* H3w = H3B + (t & 1) * H3SZ;

            {
                u64 acc[4];
                float4 bv4 = *(const float4*)(B2I + 4 * j2);
                acc[0] = pack2(bv4.x, bv4.x);
                acc[1] = pack2(bv4.y, bv4.y);
                acc[2] = pack2(bv4.z, bv4.z);
                acc[3] = pack2(bv4.w, bv4.w);
#pragma unroll 4
                for (int k = 0; k < H1; k++) {
                    const float* wr = W2XI + k * G2 + 4 * j2;
                    float4 w4 = *(const float4*)wr;
                    u64 xv = *(const u64*)(H1t + k * HP + b2);
                    acc[0] = fma2(xv, pack2(w4.x, w4.x), acc[0]);
                    acc[1] = fma2(xv, pack2(w4.y, w4.y), acc[1]);
                    acc[2] = fma2(xv, pack2(w4.z, w4.z), acc[2]);
                    acc[3] = fma2(xv, pack2(w4.w, w4.w), acc[3]);
                }
#pragma unroll 4
                for (int k = 0; k < H2; k++) {
                    const float* wr = W2HI + k * G2 + 4 * j2;
                    float4 w4 = *(const float4*)wr;
                    u64 xv = *(const u64*)(H2r + k * HP + b2);
                    acc[0] = fma2(xv, pack2(w4.x, w4.x), acc[0]);
                    acc[1] = fma2(xv, pack2(w4.y, w4.y), acc[1]);
                    acc[2] = fma2(xv, pack2(w4.z, w4.z), acc[2]);
                    acc[3] = fma2(xv, pack2(w4.w, w4.w), acc[3]);
                }
                float2 ai = u2f2(acc[0]);
                float2 af = u2f2(acc[1]);
                float2 ag = u2f2(acc[2]);
                float2 ao = u2f2(acc[3]);
                float h2v[2];
#pragma unroll
                for (int m = 0; m < 2; m++) {
                    float iv = sigf(m ? ai.y : ai.x);
                    float fv = sigf(m ? af.y : af.x);
                    float gv = tanhf_(m ? ag.y : ag.x);
                    float ov = sigf(m ? ao.y : ao.x);
                    float c = fv * c2[m] + iv * gv;
                    c2[m] = c;
                    h2v[m] = ov * tanhf_(c);
                }
                float2 hv; hv.x = h2v[0]; hv.y = h2v[1];
                *(float2*)(H2w + j2 * HP + b2) = hv;
            }
            asm volatile("bar.sync 1, 256;" ::: "memory");

            {
                u64 aif = *(const u64*)(B3I + 4 * j3);
                u64 ago = *(const u64*)(B3I + 4 * j3 + 2);
#pragma unroll 4
                for (int k = 0; k < H2; k++) {
                    ulonglong2 w = *(const ulonglong2*)(W3XI + k * G3 + 4 * j3);
                    float s = H2w[k * HP + b3];
                    u64 ss = pack2(s, s);
                    aif = fma2(ss, w.x, aif);
                    ago = fma2(ss, w.y, ago);
                }
#pragma unroll
                for (int k = 0; k < H3; k++) {
                    ulonglong2 w = *(const ulonglong2*)(W3HI + k * G3 + 4 * j3);
                    float s = H3r[k * HP + b3];
                    u64 ss = pack2(s, s);
                    aif = fma2(ss, w.x, aif);
                    ago = fma2(ss, w.y, ago);
                }
                float2 vif = u2f2(aif), vgo = u2f2(ago);
                float iv = sigf(vif.x);
                float fv = sigf(vif.y);
                float gv = tanhf_(vgo.x);
                float ov = sigf(vgo.y);
                float c = fv * c3 + iv * gv;
                c3 = c;
                H3w[j3 * HP + b3] = ov * tanhf_(c);
            }
        }
        __syncthreads();
    }

    if (tid < BTB) {
        const float* H3f = H3B + H3SZ;
        float acc = fc_b[0];
#pragma unroll
        for (int j = 0; j < H3; j++) acc += fc_w[j] * H3f[j * HP + tid];
        out[cta * BTB + tid] = acc;
    }
}

extern "C" void kernel_launch(void* const* d_in, const int* in_sizes, int n_in,
                              void* d_out, int out_size) {
    (void)in_sizes; (void)n_in; (void)out_size;
    const float* x     = (const float*)d_in[0];
    const float* w_ih1 = (const float*)d_in[1];
    const float* w_hh1 = (const float*)d_in[2];
    const float* b_ih1 = (const float*)d_in[3];
    const float* b_hh1 = (const float*)d_in[4];
    const float* w_ih2 = (const float*)d_in[5];
    const float* w_hh2 = (const float*)d_in[6];
    const float* b_ih2 = (const float*)d_in[7];
    const float* b_hh2 = (const float*)d_in[8];
    const float* w_ih3 = (const float*)d_in[9];
    const float* w_hh3 = (const float*)d_in[10];
    const float* b_ih3 = (const float*)d_in[11];
    const float* b_hh3 = (const float*)d_in[12];
    const float* fc_w  = (const float*)d_in[13];
    const float* fc_b  = (const float*)d_in[14];
    float* out = (float*)d_out;

    cudaFuncSetAttribute(lstm_phaseA_mma,
                         cudaFuncAttributeMaxDynamicSharedMemorySize, A_SMEM_BYTES);
    cudaFuncSetAttribute(lstm_phaseB,
                         cudaFuncAttributeMaxDynamicSharedMemorySize, B_SMEM_BYTES);

    lstm_phaseA_mma<<<NBLK_A, NTM_A, A_SMEM_BYTES>>>(x, w_ih1, b_ih1, b_hh1);
    lstm_phaseB<<<NCTA_B, NTB, B_SMEM_BYTES>>>(
        w_hh1, w_ih2, w_hh2, b_ih2, b_hh2,
        w_ih3, w_hh3, b_ih3, b_hh3, fc_w, fc_b, out);
}

// round 11
// speedup vs baseline: 1.4683x; 1.0933x over previous
#include <cuda_runtime.h>
#include <cuda_bf16.h>
#include <cstdint>

typedef unsigned long long u64;

#define TT    64
#define BATCH 8192
#define DIN   128

#define G1 128
#define G2 64
#define G3 32
#define H1 32
#define H2 16
#define H3 8

// ---------------- phase A (mma.sync bf16 split GEMM, M=64 tiles) ----------------
#define NTM_A 256
#define TPB_A 8
#define NBLK_A 1024                     // 8192 tiles / 8
#define PW 68                           // smem pitch in 32-bit words
#define XH_OFF 0                        // 64 rows
#define XL_OFF (64 * PW * 4)            // 17408
#define WH_OFF (2 * 64 * PW * 4)        // 34816 (128 rows)
#define WL_OFF (WH_OFF + 128 * PW * 4)  // 69632
#define A_SMEM_BYTES (WL_OFF + 128 * PW * 4)   // 104448 -> 2 CTAs/SM

// ---------------- phase B (recurrent, BT=32, warp-specialized) ----------------
#define BTB  32
#define NCTA_B (BATCH / BTB)
#define NTB 512
#define HP 36
#define H1SZ (H1 * HP)
#define H2SZ (H2 * HP)
#define H3SZ (H3 * HP)
#define OFFB_W1HI 0
#define OFFB_W2XI 4096
#define OFFB_W2HI 6144
#define OFFB_B2I  7168
#define OFFB_W3XI 7232
#define OFFB_W3HI 7744
#define OFFB_B3I  8000
#define OFFB_H1   8032
#define OFFB_H2   (OFFB_H1 + 2 * H1SZ)
#define OFFB_H3   (OFFB_H2 + 2 * H2SZ)
#define B_SMEM_FLOATS (OFFB_H3 + 2 * H3SZ)
#define B_SMEM_BYTES  (B_SMEM_FLOATS * 4)

// 256 MB scratch: XG[r = b*64 + t][n = 4j+q]  (row-major, bias folded in)
__device__ float g_xg[(size_t)BATCH * TT * G1];

// ======================= common helpers =======================
__device__ __forceinline__ u64 pack2(float a, float b) {
    u64 r;
    asm("mov.b64 %0, {%1, %2};" : "=l"(r) : "f"(a), "f"(b));
    return r;
}
__device__ __forceinline__ u64 fma2(u64 a, u64 b, u64 c) {
    u64 d;
    asm("fma.rn.f32x2 %0, %1, %2, %3;" : "=l"(d) : "l"(a), "l"(b), "l"(c));
    return d;
}
__device__ __forceinline__ float2 u2f2(u64 v) {
    float2 r;
    asm("mov.b64 {%0, %1}, %2;" : "=f"(r.x), "=f"(r.y) : "l"(v));
    return r;
}
__device__ __forceinline__ float sigf(float v) {
    return __fdividef(1.f, 1.f + __expf(-v));
}
__device__ __forceinline__ float tanhf_(float v) {
    return 1.f - __fdividef(2.f, __expf(2.f * v) + 1.f);
}

__device__ __forceinline__ void mma_bf16(float (&d)[4],
                                         uint32_t a0, uint32_t a1,
                                         uint32_t a2, uint32_t a3,
                                         uint32_t b0, uint32_t b1) {
    asm volatile(
        "mma.sync.aligned.m16n8k16.row.col.f32.bf16.bf16.f32 "
        "{%0,%1,%2,%3}, {%4,%5,%6,%7}, {%8,%9}, {%0,%1,%2,%3};"
        : "+f"(d[0]), "+f"(d[1]), "+f"(d[2]), "+f"(d[3])
        : "r"(a0), "r"(a1), "r"(a2), "r"(a3), "r"(b0), "r"(b1));
}

// convert 2*N floats into hi/lo bf16x2 words
template <int N>
__device__ __forceinline__ void stage_rowN(const float* __restrict__ src,
                                           uint32_t* __restrict__ H,
                                           uint32_t* __restrict__ L) {
#pragma unroll
    for (int i = 0; i < N; i++) {
        float4 v = ((const float4*)src)[i];
        __nv_bfloat162 h0 = __float22bfloat162_rn(make_float2(v.x, v.y));
        float2 f0 = __bfloat1622float2(h0);
        __nv_bfloat162 l0 = __float22bfloat162_rn(make_float2(v.x - f0.x, v.y - f0.y));
        __nv_bfloat162 h1 = __float22bfloat162_rn(make_float2(v.z, v.w));
        float2 f1 = __bfloat1622float2(h1);
        __nv_bfloat162 l1 = __float22bfloat162_rn(make_float2(v.z - f1.x, v.w - f1.y));
        H[2 * i]     = *(uint32_t*)&h0;
        H[2 * i + 1] = *(uint32_t*)&h1;
        L[2 * i]     = *(uint32_t*)&l0;
        L[2 * i + 1] = *(uint32_t*)&l1;
    }
}

// ======================= PHASE A (HMMA, M=64) =======================
// XG[r][4j+q] = sum_k x[r][k] * w_ih1[q*32+j][k] + b1[q*32+j]
extern __shared__ char smA[];
__global__ __launch_bounds__(NTM_A, 2) void lstm_phaseA_mma(
    const float* __restrict__ x,
    const float* __restrict__ w_ih1,
    const float* __restrict__ b_ih1,
    const float* __restrict__ b_hh1) {
    uint32_t* XH = (uint32_t*)(smA + XH_OFF);
    uint32_t* XL = (uint32_t*)(smA + XL_OFF);
    uint32_t* WH = (uint32_t*)(smA + WH_OFF);
    uint32_t* WL = (uint32_t*)(smA + WL_OFF);

    const int tid = threadIdx.x;
    const int wid = tid >> 5, lid = tid & 31;
    const int g = lid >> 2, tig = lid & 3;
    const int m0w = (wid & 1) * 32;      // warp M offset (0 or 32)
    const int n0w = (wid >> 1) * 32;     // warp N offset (0..96)

    // bias for this thread's D columns (n, n+1) per n-frag
    float2 biasp[4];
#pragma unroll
    for (int nf = 0; nf < 4; nf++) {
        int n = n0w + nf * 8 + tig * 2;
        int ga = ((n & 3) << 5) + (n >> 2);
        int gb = (((n + 1) & 3) << 5) + ((n + 1) >> 2);
        biasp[nf].x = b_ih1[ga] + b_hh1[ga];
        biasp[nf].y = b_ih1[gb] + b_hh1[gb];
    }

    // stage W hi/lo once: row n of W^T = w_ih1 row g(n)
    {
        int row = tid >> 1, c0 = (tid & 1) * 64;
        int gw = ((row & 3) << 5) + (row >> 2);
        stage_rowN<16>(w_ih1 + (size_t)gw * DIN + c0,
                       WH + row * PW + (c0 >> 1), WL + row * PW + (c0 >> 1));
    }

    for (int tt = 0; tt < TPB_A; tt++) {
        const size_t r0 = ((size_t)blockIdx.x * TPB_A + tt) * 64;
        {
            int row = tid >> 2, c0 = (tid & 3) * 32;
            stage_rowN<8>(x + (r0 + row) * DIN + c0,
                          XH + row * PW + (c0 >> 1), XL + row * PW + (c0 >> 1));
        }
        __syncthreads();   // W (first iter) + X staged

        float acc[2][4][4];
#pragma unroll
        for (int mi = 0; mi < 2; mi++)
#pragma unroll
            for (int nf = 0; nf < 4; nf++) {
                acc[mi][nf][0] = biasp[nf].x;
                acc[mi][nf][1] = biasp[nf].y;
                acc[mi][nf][2] = biasp[nf].x;
                acc[mi][nf][3] = biasp[nf].y;
            }

#pragma unroll
        for (int ks = 0; ks < 8; ks++) {
            uint32_t ah[2][4], al[2][4];
#pragma unroll
            for (int mi = 0; mi < 2; mi++) {
                int base = (m0w + mi * 16 + g) * PW + tig + ks * 8;
                ah[mi][0] = XH[base];
                ah[mi][1] = XH[base + 8 * PW];
                ah[mi][2] = XH[base + 4];
                ah[mi][3] = XH[base + 8 * PW + 4];
                al[mi][0] = XL[base];
                al[mi][1] = XL[base + 8 * PW];
                al[mi][2] = XL[base + 4];
                al[mi][3] = XL[base + 8 * PW + 4];
            }
#pragma unroll
            for (int nf = 0; nf < 4; nf++) {
                int wb = (n0w + nf * 8 + g) * PW + tig + ks * 8;
                uint32_t bh0 = WH[wb], bh1 = WH[wb + 4];
                uint32_t bl0 = WL[wb], bl1 = WL[wb + 4];
#pragma unroll
                for (int mi = 0; mi < 2; mi++) {
                    mma_bf16(acc[mi][nf], ah[mi][0], ah[mi][1], ah[mi][2], ah[mi][3], bh0, bh1);
                    mma_bf16(acc[mi][nf], ah[mi][0], ah[mi][1], ah[mi][2], ah[mi][3], bl0, bl1);
                    mma_bf16(acc[mi][nf], al[mi][0], al[mi][1], al[mi][2], al[mi][3], bh0, bh1);
                }
            }
        }

        // epilogue: D frags straight to row-major XG
#pragma unroll
        for (int mi = 0; mi < 2; mi++) {
            size_t row = r0 + m0w + mi * 16 + g;
#pragma unroll
            for (int nf = 0; nf < 4; nf++) {
                int col = n0w + nf * 8 + tig * 2;
                float2 v0; v0.x = acc[mi][nf][0]; v0.y = acc[mi][nf][1];
                float2 v1; v1.x = acc[mi][nf][2]; v1.y = acc[mi][nf][3];
                *(float2*)(g_xg + row * G1 + col) = v0;
                *(float2*)(g_xg + (row + 8) * G1 + col) = v1;
            }
        }
        __syncthreads();   // before restaging X
    }
}

// ======================= PHASE B =======================
__device__ __forceinline__ void stage1_step(
    int tn, int bg0, const float* __restrict__ W1HI,
    float* __restrict__ H1B, float4 (&xg)[4], float (&c1)[4],
    int j1, int b1) {
    const float* H1r = H1B + ((tn + 1) & 1) * H1SZ;
    float* H1w = H1B + (tn & 1) * H1SZ;

    const float* x0 = (const float*)&xg[0];
    const float* x1 = (const float*)&xg[1];
    const float* x2 = (const float*)&xg[2];
    const float* x3 = (const float*)&xg[3];
    u64 acc[4][2];
#pragma unroll
    for (int q = 0; q < 4; q++) {
        acc[q][0] = pack2(x0[q], x1[q]);
        acc[q][1] = pack2(x2[q], x3[q]);
    }
#pragma unroll 4
    for (int k = 0; k < H1; k++) {
        const float* wr = W1HI + k * G1 + 4 * j1;
        float4 w4 = *(const float4*)wr;
        u64 wd0 = pack2(w4.x, w4.x);
        u64 wd1 = pack2(w4.y, w4.y);
        u64 wd2 = pack2(w4.z, w4.z);
        u64 wd3 = pack2(w4.w, w4.w);
        ulonglong2 xv = *(const ulonglong2*)(H1r + k * HP + b1);
        acc[0][0] = fma2(xv.x, wd0, acc[0][0]);
        acc[0][1] = fma2(xv.y, wd0, acc[0][1]);
        acc[1][0] = fma2(xv.x, wd1, acc[1][0]);
        acc[1][1] = fma2(xv.y, wd1, acc[1][1]);
        acc[2][0] = fma2(xv.x, wd2, acc[2][0]);
        acc[2][1] = fma2(xv.y, wd2, acc[2][1]);
        acc[3][0] = fma2(xv.x, wd3, acc[3][0]);
        acc[3][1] = fma2(xv.y, wd3, acc[3][1]);
    }
    if (tn + 1 < TT) {
#pragma unroll
        for (int i = 0; i < 4; i++)
            xg[i] = *(const float4*)(g_xg +
                ((size_t)(bg0 + i) * TT + tn + 1) * G1 + 4 * j1);
    }
    float h4[4];
#pragma unroll
    for (int p = 0; p < 2; p++) {
        float2 ai = u2f2(acc[0][p]);
        float2 af = u2f2(acc[1][p]);
        float2 ag = u2f2(acc[2][p]);
        float2 ao = u2f2(acc[3][p]);
#pragma unroll
        for (int m = 0; m < 2; m++) {
            int e = 2 * p + m;
            float iv = sigf(m ? ai.y : ai.x);
            float fv = sigf(m ? af.y : af.x);
            float gv = tanhf_(m ? ag.y : ag.x);
            float ov = sigf(m ? ao.y : ao.x);
            float c = fv * c1[e] + iv * gv;
            c1[e] = c;
            h4[e] = ov * tanhf_(c);
        }
    }
    float4 hv; hv.x = h4[0]; hv.y = h4[1]; hv.z = h4[2]; hv.w = h4[3];
    *(float4*)(H1w + j1 * HP + b1) = hv;
}

extern __shared__ float smemB[];
__global__ __launch_bounds__(NTB, 2) void lstm_phaseB(
    const float* __restrict__ w_hh1,
    const float* __restrict__ w_ih2, const float* __restrict__ w_hh2,
    const float* __restrict__ b_ih2, const float* __restrict__ b_hh2,
    const float* __restrict__ w_ih3, const float* __restrict__ w_hh3,
    const float* __restrict__ b_ih3, const float* __restrict__ b_hh3,
    const float* __restrict__ fc_w, const float* __restrict__ fc_b,
    float* __restrict__ out) {
    const int tid = threadIdx.x;
    const int cta = blockIdx.x;

    float* W1HI = smemB + OFFB_W1HI;
    float* W2XI = smemB + OFFB_W2XI;
    float* W2HI = smemB + OFFB_W2HI;
    float* B2I  = smemB + OFFB_B2I;
    float* W3XI = smemB + OFFB_W3XI;
    float* W3HI = smemB + OFFB_W3HI;
    float* B3I  = smemB + OFFB_B3I;
    float* H1B  = smemB + OFFB_H1;
    float* H2B  = smemB + OFFB_H2;
    float* H3B  = smemB + OFFB_H3;

    for (int i = tid; i < G1 * H1; i += NTB) {
        int g = i >> 5, k = i & 31;
        W1HI[k * G1 + 4 * (g & 31) + (g >> 5)] = w_hh1[i];
    }
    for (int i = tid; i < G2 * H1; i += NTB) {
        int g = i >> 5, k = i & 31;
        W2XI[k * G2 + 4 * (g & 15) + (g >> 4)] = w_ih2[i];
    }
    for (int i = tid; i < G2 * H2; i += NTB) {
        int g = i >> 4, k = i & 15;
        W2HI[k * G2 + 4 * (g & 15) + (g >> 4)] = w_hh2[i];
    }
    for (int i = tid; i < G2; i += NTB)
        B2I[4 * (i & 15) + (i >> 4)] = b_ih2[i] + b_hh2[i];
    for (int i = tid; i < G3 * H2; i += NTB) {
        int g = i >> 4, k = i & 15;
        W3XI[k * G3 + 4 * (g & 7) + (g >> 3)] = w_ih3[i];
    }
    for (int i = tid; i < G3 * H3; i += NTB) {
        int g = i >> 3, k = i & 7;
        W3HI[k * G3 + 4 * (g & 7) + (g >> 3)] = w_hh3[i];
    }
    for (int i = tid; i < G3; i += NTB)
        B3I[4 * (i & 7) + (i >> 3)] = b_ih3[i] + b_hh3[i];
    for (int i = tid; i < 2 * H1SZ; i += NTB) H1B[i] = 0.f;
    for (int i = tid; i < 2 * H2SZ; i += NTB) H2B[i] = 0.f;
    for (int i = tid; i < 2 * H3SZ; i += NTB) H3B[i] = 0.f;

    // group A (warps 0-7): L1, 1 j x 4 batch.
    // REMAP: lanes vary in j1 -> XG LDG coalesces into 512B lines; H1r broadcasts.
    const int j1 = tid & 31;
    const int b1 = ((tid >> 5) & 7) * 4;
    const int bg0 = cta * BTB + b1;
    float c1[4] = {0.f, 0.f, 0.f, 0.f};
    float4 xg[4];

    // group B (warps 8-15)
    const int tid2 = tid - 256;
    const int j2 = tid2 >> 4;
    const int b2 = (tid2 & 15) * 2;
    const int j3 = tid2 >> 5;
    const int b3 = tid2 & 31;
    float c2[2] = {0.f, 0.f};
    float c3 = 0.f;

    if (tid < 256) {
#pragma unroll
        for (int i = 0; i < 4; i++)
            xg[i] = *(const float4*)(g_xg + (size_t)(bg0 + i) * TT * G1 + 4 * j1);
    }
    __syncthreads();

    if (tid < 256)
        stage1_step(0, bg0, W1HI, H1B, xg, c1, j1, b1);
    __syncthreads();

    for (int t = 0; t < TT; ++t) {
        if (tid < 256) {
            if (t + 1 < TT)
                stage1_step(t + 1, bg0, W1HI, H1B, xg, c1, j1, b1);
        } else {
            const float* H1t = H1B + (t & 1) * H1SZ;
            const float* H2r = H2B + ((t + 1) & 1) * H2SZ;
            float* H2w = H2B + (t & 1) * H2SZ;
            const float* H3r = H3B + ((t + 1) & 1) * H3SZ;
            float* H3w = H3B + (t & 1) * H3SZ;

            {
                u64 acc[4];
                float4 bv4 = *(const float4*)(B2I + 4 * j2);
                acc[0] = pack2(bv4.x, bv4.x);
                acc[1] = pack2(bv4.y, bv4.y);
                acc[2] = pack2(bv4.z, bv4.z);
                acc[3] = pack2(bv4.w, bv4.w);
#pragma unroll 4
                for (int k = 0; k < H1; k++) {
                    const float* wr = W2XI + k * G2 + 4 * j2;
                    float4 w4 = *(const float4*)wr;
                    u64 xv = *(const u64*)(H1t + k * HP + b2);
                    acc[0] = fma2(xv, pack2(w4.x, w4.x), acc[0]);
                    acc[1] = fma2(xv, pack2(w4.y, w4.y), acc[1]);
                    acc[2] = fma2(xv, pack2(w4.z, w4.z), acc[2]);
                    acc[3] = fma2(xv, pack2(w4.w, w4.w), acc[3]);
                }
#pragma unroll 4
                for (int k = 0; k < H2; k++) {
                    const float* wr = W2HI + k * G2 + 4 * j2;
                    float4 w4 = *(const float4*)wr;
                    u64 xv = *(const u64*)(H2r + k * HP + b2);
                    acc[0] = fma2(xv, pack2(w4.x, w4.x), acc[0]);
                    acc[1] = fma2(xv, pack2(w4.y, w4.y), acc[1]);
                    acc[2] = fma2(xv, pack2(w4.z, w4.z), acc[2]);
                    acc[3] = fma2(xv, pack2(w4.w, w4.w), acc[3]);
                }
                float2 ai = u2f2(acc[0]);
                float2 af = u2f2(acc[1]);
                float2 ag = u2f2(acc[2]);
                float2 ao = u2f2(acc[3]);
                float h2v[2];
#pragma unroll
                for (int m = 0; m < 2; m++) {
                    float iv = sigf(m ? ai.y : ai.x);
                    float fv = sigf(m ? af.y : af.x);
                    float gv = tanhf_(m ? ag.y : ag.x);
                    float ov = sigf(m ? ao.y : ao.x);
                    float c = fv * c2[m] + iv * gv;
                    c2[m] = c;
                    h2v[m] = ov * tanhf_(c);
                }
                float2 hv; hv.x = h2v[0]; hv.y = h2v[1];
                *(float2*)(H2w + j2 * HP + b2) = hv;
            }
            asm volatile("bar.sync 1, 256;" ::: "memory");

            {
                u64 aif = *(const u64*)(B3I + 4 * j3);
                u64 ago = *(const u64*)(B3I + 4 * j3 + 2);
#pragma unroll 4
                for (int k = 0; k < H2; k++) {
                    ulonglong2 w = *(const ulonglong2*)(W3XI + k * G3 + 4 * j3);
                    float s = H2w[k * HP + b3];
                    u64 ss = pack2(s, s);
                    aif = fma2(ss, w.x, aif);
                    ago = fma2(ss, w.y, ago);
                }
#pragma unroll
                for (int k = 0; k < H3; k++) {
                    ulonglong2 w = *(const ulonglong2*)(W3HI + k * G3 + 4 * j3);
                    float s = H3r[k * HP + b3];
                    u64 ss = pack2(s, s);
                    aif = fma2(ss, w.x, aif);
                    ago = fma2(ss, w.y, ago);
                }
                float2 vif = u2f2(aif), vgo = u2f2(ago);
                float iv = sigf(vif.x);
                float fv = sigf(vif.y);
                float gv = tanhf_(vgo.x);
                float ov = sigf(vgo.y);
                float c = fv * c3 + iv * gv;
                c3 = c;
                H3w[j3 * HP + b3] = ov * tanhf_(c);
            }
        }
        __syncthreads();
    }

    if (tid < BTB) {
        const float* H3f = H3B + H3SZ;
        float acc = fc_b[0];
#pragma unroll
        for (int j = 0; j < H3; j++) acc += fc_w[j] * H3f[j * HP + tid];
        out[cta * BTB + tid] = acc;
    }
}

extern "C" void kernel_launch(void* const* d_in, const int* in_sizes, int n_in,
                              void* d_out, int out_size) {
    (void)in_sizes; (void)n_in; (void)out_size;
    const float* x     = (const float*)d_in[0];
    const float* w_ih1 = (const float*)d_in[1];
    const float* w_hh1 = (const float*)d_in[2];
    const float* b_ih1 = (const float*)d_in[3];
    const float* b_hh1 = (const float*)d_in[4];
    const float* w_ih2 = (const float*)d_in[5];
    const float* w_hh2 = (const float*)d_in[6];
    const float* b_ih2 = (const float*)d_in[7];
    const float* b_hh2 = (const float*)d_in[8];
    const float* w_ih3 = (const float*)d_in[9];
    const float* w_hh3 = (const float*)d_in[10];
    const float* b_ih3 = (const float*)d_in[11];
    const float* b_hh3 = (const float*)d_in[12];
    const float* fc_w  = (const float*)d_in[13];
    const float* fc_b  = (const float*)d_in[14];
    float* out = (float*)d_out;

    cudaFuncSetAttribute(lstm_phaseA_mma,
                         cudaFuncAttributeMaxDynamicSharedMemorySize, A_SMEM_BYTES);
    cudaFuncSetAttribute(lstm_phaseB,
                         cudaFuncAttributeMaxDynamicSharedMemorySize, B_SMEM_BYTES);

    lstm_phaseA_mma<<<NBLK_A, NTM_A, A_SMEM_BYTES>>>(x, w_ih1, b_ih1, b_hh1);
    lstm_phaseB<<<NCTA_B, NTB, B_SMEM_BYTES>>>(
        w_hh1, w_ih2, w_hh2, b_ih2, b_hh2,
        w_ih3, w_hh3, b_ih3, b_hh3, fc_w, fc_b, out);
}

// round 12
// speedup vs baseline: 1.5275x; 1.0403x over previous
#include <cuda_runtime.h>
#include <cuda_bf16.h>
#include <cstdint>

typedef unsigned long long u64;

#define TT    64
#define BATCH 8192
#define DIN   128

#define G1 128
#define G2 64
#define G3 32
#define H1 32
#define H2 16
#define H3 8

// ---------------- phase A (mma.sync bf16 split GEMM, M=64 tiles) ----------------
#define NTM_A 256
#define TPB_A 8
#define NBLK_A 1024                     // 8192 tiles / 8
#define PW 68                           // smem pitch in 32-bit words
#define XH_OFF 0                        // 64 rows
#define XL_OFF (64 * PW * 4)            // 17408
#define WH_OFF (2 * 64 * PW * 4)        // 34816 (128 rows)
#define WL_OFF (WH_OFF + 128 * PW * 4)  // 69632
#define A_SMEM_BYTES (WL_OFF + 128 * PW * 4)   // 104448 -> 2 CTAs/SM

// ---------------- phase B (recurrent, BT=32, warp-specialized) ----------------
#define BTB  32
#define NCTA_B (BATCH / BTB)
#define NTB 512
#define HP 36
#define H1SZ (H1 * HP)
#define H2SZ (H2 * HP)
#define H3SZ (H3 * HP)
#define OFFB_W1HI 0
#define OFFB_W2XI 4096
#define OFFB_W2HI 6144
#define OFFB_B2I  7168
#define OFFB_W3XI 7232
#define OFFB_W3HI 7744
#define OFFB_B3I  8000
#define OFFB_H1   8032
#define OFFB_H2   (OFFB_H1 + 2 * H1SZ)
#define OFFB_H3   (OFFB_H2 + 2 * H2SZ)
#define B_SMEM_FLOATS (OFFB_H3 + 2 * H3SZ)
#define B_SMEM_BYTES  (B_SMEM_FLOATS * 4)

// 256 MB scratch: XG[r = b*64 + t][n = 4j+q]  (row-major, bias folded in)
__device__ float g_xg[(size_t)BATCH * TT * G1];

// ======================= common helpers =======================
__device__ __forceinline__ u64 pack2(float a, float b) {
    u64 r;
    asm("mov.b64 %0, {%1, %2};" : "=l"(r) : "f"(a), "f"(b));
    return r;
}
__device__ __forceinline__ u64 fma2(u64 a, u64 b, u64 c) {
    u64 d;
    asm("fma.rn.f32x2 %0, %1, %2, %3;" : "=l"(d) : "l"(a), "l"(b), "l"(c));
    return d;
}
__device__ __forceinline__ float2 u2f2(u64 v) {
    float2 r;
    asm("mov.b64 {%0, %1}, %2;" : "=f"(r.x), "=f"(r.y) : "l"(v));
    return r;
}
__device__ __forceinline__ float sigf(float v) {
    return __fdividef(1.f, 1.f + __expf(-v));
}
__device__ __forceinline__ float tanhf_(float v) {
    return 1.f - __fdividef(2.f, __expf(2.f * v) + 1.f);
}

__device__ __forceinline__ void mma_bf16(float (&d)[4],
                                         uint32_t a0, uint32_t a1,
                                         uint32_t a2, uint32_t a3,
                                         uint32_t b0, uint32_t b1) {
    asm volatile(
        "mma.sync.aligned.m16n8k16.row.col.f32.bf16.bf16.f32 "
        "{%0,%1,%2,%3}, {%4,%5,%6,%7}, {%8,%9}, {%0,%1,%2,%3};"
        : "+f"(d[0]), "+f"(d[1]), "+f"(d[2]), "+f"(d[3])
        : "r"(a0), "r"(a1), "r"(a2), "r"(a3), "r"(b0), "r"(b1));
}

// convert 4 floats (float4) into hi/lo bf16x2 word pairs
__device__ __forceinline__ void cvt4(float4 v, uint32_t* H, uint32_t* L) {
    __nv_bfloat162 h0 = __float22bfloat162_rn(make_float2(v.x, v.y));
    float2 f0 = __bfloat1622float2(h0);
    __nv_bfloat162 l0 = __float22bfloat162_rn(make_float2(v.x - f0.x, v.y - f0.y));
    __nv_bfloat162 h1 = __float22bfloat162_rn(make_float2(v.z, v.w));
    float2 f1 = __bfloat1622float2(h1);
    __nv_bfloat162 l1 = __float22bfloat162_rn(make_float2(v.z - f1.x, v.w - f1.y));
    H[0] = *(uint32_t*)&h0;
    H[1] = *(uint32_t*)&h1;
    L[0] = *(uint32_t*)&l0;
    L[1] = *(uint32_t*)&l1;
}

// ======================= PHASE A (HMMA, M=64, x reg-prefetch) =======================
// XG[r][4j+q] = sum_k x[r][k] * w_ih1[q*32+j][k] + b1[q*32+j]
extern __shared__ char smA[];
__global__ __launch_bounds__(NTM_A, 2) void lstm_phaseA_mma(
    const float* __restrict__ x,
    const float* __restrict__ w_ih1,
    const float* __restrict__ b_ih1,
    const float* __restrict__ b_hh1) {
    uint32_t* XH = (uint32_t*)(smA + XH_OFF);
    uint32_t* XL = (uint32_t*)(smA + XL_OFF);
    uint32_t* WH = (uint32_t*)(smA + WH_OFF);
    uint32_t* WL = (uint32_t*)(smA + WL_OFF);

    const int tid = threadIdx.x;
    const int wid = tid >> 5, lid = tid & 31;
    const int g = lid >> 2, tig = lid & 3;
    const int m0w = (wid & 1) * 32;      // warp M offset (0 or 32)
    const int n0w = (wid >> 1) * 32;     // warp N offset (0..96)

    // bias for this thread's D columns (n, n+1) per n-frag
    float2 biasp[4];
#pragma unroll
    for (int nf = 0; nf < 4; nf++) {
        int n = n0w + nf * 8 + tig * 2;
        int ga = ((n & 3) << 5) + (n >> 2);
        int gb = (((n + 1) & 3) << 5) + ((n + 1) >> 2);
        biasp[nf].x = b_ih1[ga] + b_hh1[ga];
        biasp[nf].y = b_ih1[gb] + b_hh1[gb];
    }

    // stage W hi/lo once: row n of W^T = w_ih1 row g(n)
    {
        int row = tid >> 1, c0 = (tid & 1) * 64;
        int gw = ((row & 3) << 5) + (row >> 2);
        const float* src = w_ih1 + (size_t)gw * DIN + c0;
        uint32_t* Hd = WH + row * PW + (c0 >> 1);
        uint32_t* Ld = WL + row * PW + (c0 >> 1);
#pragma unroll
        for (int i = 0; i < 16; i++)
            cvt4(((const float4*)src)[i], Hd + 2 * i, Ld + 2 * i);
    }

    // x staging assignment: row = tid>>2 (0..63), c0 = (tid&3)*32 (32 floats)
    const int xrow = tid >> 2;
    const int xc0 = (tid & 3) * 32;
    float4 xr[8];
#define LOADX_A(tt_)                                                        \
    {                                                                       \
        const float4* p = (const float4*)(x +                               \
            (((size_t)blockIdx.x * TPB_A + (tt_)) * 64 + xrow) * DIN + xc0); \
        _Pragma("unroll") for (int i = 0; i < 8; i++) xr[i] = p[i];         \
    }

    LOADX_A(0);

    for (int tt = 0; tt < TPB_A; tt++) {
        const size_t r0 = ((size_t)blockIdx.x * TPB_A + tt) * 64;
        // stage x tile tt from registers (convert + STS only)
        {
            uint32_t* Hd = XH + xrow * PW + (xc0 >> 1);
            uint32_t* Ld = XL + xrow * PW + (xc0 >> 1);
#pragma unroll
            for (int i = 0; i < 8; i++)
                cvt4(xr[i], Hd + 2 * i, Ld + 2 * i);
        }
        __syncthreads();   // W (first iter) + X(tt) staged

        // prefetch x for tile tt+1; covered by MMA + epilogue below
        if (tt + 1 < TPB_A) LOADX_A(tt + 1);

        float acc[2][4][4];
#pragma unroll
        for (int mi = 0; mi < 2; mi++)
#pragma unroll
            for (int nf = 0; nf < 4; nf++) {
                acc[mi][nf][0] = biasp[nf].x;
                acc[mi][nf][1] = biasp[nf].y;
                acc[mi][nf][2] = biasp[nf].x;
                acc[mi][nf][3] = biasp[nf].y;
            }

#pragma unroll
        for (int ks = 0; ks < 8; ks++) {
            uint32_t ah[2][4], al[2][4];
#pragma unroll
            for (int mi = 0; mi < 2; mi++) {
                int base = (m0w + mi * 16 + g) * PW + tig + ks * 8;
                ah[mi][0] = XH[base];
                ah[mi][1] = XH[base + 8 * PW];
                ah[mi][2] = XH[base + 4];
                ah[mi][3] = XH[base + 8 * PW + 4];
                al[mi][0] = XL[base];
                al[mi][1] = XL[base + 8 * PW];
                al[mi][2] = XL[base + 4];
                al[mi][3] = XL[base + 8 * PW + 4];
            }
#pragma unroll
            for (int nf = 0; nf < 4; nf++) {
                int wb = (n0w + nf * 8 + g) * PW + tig + ks * 8;
                uint32_t bh0 = WH[wb], bh1 = WH[wb + 4];
                uint32_t bl0 = WL[wb], bl1 = WL[wb + 4];
#pragma unroll
                for (int mi = 0; mi < 2; mi++) {
                    mma_bf16(acc[mi][nf], ah[mi][0], ah[mi][1], ah[mi][2], ah[mi][3], bh0, bh1);
                    mma_bf16(acc[mi][nf], ah[mi][0], ah[mi][1], ah[mi][2], ah[mi][3], bl0, bl1);
                    mma_bf16(acc[mi][nf], al[mi][0], al[mi][1], al[mi][2], al[mi][3], bh0, bh1);
                }
            }
        }

        // epilogue: D frags straight to row-major XG
#pragma unroll
        for (int mi = 0; mi < 2; mi++) {
            size_t row = r0 + m0w + mi * 16 + g;
#pragma unroll
            for (int nf = 0; nf < 4; nf++) {
                int col = n0w + nf * 8 + tig * 2;
                float2 v0; v0.x = acc[mi][nf][0]; v0.y = acc[mi][nf][1];
                float2 v1; v1.x = acc[mi][nf][2]; v1.y = acc[mi][nf][3];
                *(float2*)(g_xg + row * G1 + col) = v0;
                *(float2*)(g_xg + (row + 8) * G1 + col) = v1;
            }
        }
        __syncthreads();   // all reads of X(tt) done before restaging
    }
}

// ======================= PHASE B =======================
__device__ __forceinline__ void stage1_step(
    int tn, int bg0, const float* __restrict__ W1HI,
    float* __restrict__ H1B, float4 (&xg)[4], float (&c1)[4],
    int j1, int b1) {
    const float* H1r = H1B + ((tn + 1) & 1) * H1SZ;
    float* H1w = H1B + (tn & 1) * H1SZ;

    const float* x0 = (const float*)&xg[0];
    const float* x1 = (const float*)&xg[1];
    const float* x2 = (const float*)&xg[2];
    const float* x3 = (const float*)&xg[3];
    u64 acc[4][2];
#pragma unroll
    for (int q = 0; q < 4; q++) {
        acc[q][0] = pack2(x0[q], x1[q]);
        acc[q][1] = pack2(x2[q], x3[q]);
    }
#pragma unroll 4
    for (int k = 0; k < H1; k++) {
        const float* wr = W1HI + k * G1 + 4 * j1;
        float4 w4 = *(const float4*)wr;
        u64 wd0 = pack2(w4.x, w4.x);
        u64 wd1 = pack2(w4.y, w4.y);
        u64 wd2 = pack2(w4.z, w4.z);
        u64 wd3 = pack2(w4.w, w4.w);
        ulonglong2 xv = *(const ulonglong2*)(H1r + k * HP + b1);
        acc[0][0] = fma2(xv.x, wd0, acc[0][0]);
        acc[0][1] = fma2(xv.y, wd0, acc[0][1]);
        acc[1][0] = fma2(xv.x, wd1, acc[1][0]);
        acc[1][1] = fma2(xv.y, wd1, acc[1][1]);
        acc[2][0] = fma2(xv.x, wd2, acc[2][0]);
        acc[2][1] = fma2(xv.y, wd2, acc[2][1]);
        acc[3][0] = fma2(xv.x, wd3, acc[3][0]);
        acc[3][1] = fma2(xv.y, wd3, acc[3][1]);
    }
    if (tn + 1 < TT) {
#pragma unroll
        for (int i = 0; i < 4; i++)
            xg[i] = *(const float4*)(g_xg +
                ((size_t)(bg0 + i) * TT + tn + 1) * G1 + 4 * j1);
    }
    float h4[4];
#pragma unroll
    for (int p = 0; p < 2; p++) {
        float2 ai = u2f2(acc[0][p]);
        float2 af = u2f2(acc[1][p]);
        float2 ag = u2f2(acc[2][p]);
        float2 ao = u2f2(acc[3][p]);
#pragma unroll
        for (int m = 0; m < 2; m++) {
            int e = 2 * p + m;
            float iv = sigf(m ? ai.y : ai.x);
            float fv = sigf(m ? af.y : af.x);
            float gv = tanhf_(m ? ag.y : ag.x);
            float ov = sigf(m ? ao.y : ao.x);
            float c = fv * c1[e] + iv * gv;
            c1[e] = c;
            h4[e] = ov * tanhf_(c);
        }
    }
    float4 hv; hv.x = h4[0]; hv.y = h4[1]; hv.z = h4[2]; hv.w = h4[3];
    *(float4*)(H1w + j1 * HP + b1) = hv;
}

extern __shared__ float smemB[];
__global__ __launch_bounds__(NTB, 2) void lstm_phaseB(
    const float* __restrict__ w_hh1,
    const float* __restrict__ w_ih2, const float* __restrict__ w_hh2,
    const float* __restrict__ b_ih2, const float* __restrict__ b_hh2,
    const float* __restrict__ w_ih3, const float* __restrict__ w_hh3,
    const float* __restrict__ b_ih3, const float* __restrict__ b_hh3,
    const float* __restrict__ fc_w, const float* __restrict__ fc_b,
    float* __restrict__ out) {
    const int tid = threadIdx.x;
    const int cta = blockIdx.x;

    float* W1HI = smemB + OFFB_W1HI;
    float* W2XI = smemB + OFFB_W2XI;
    float* W2HI = smemB + OFFB_W2HI;
    float* B2I  = smemB + OFFB_B2I;
    float* W3XI = smemB + OFFB_W3XI;
    float* W3HI = smemB + OFFB_W3HI;
    float* B3I  = smemB + OFFB_B3I;
    float* H1B  = smemB + OFFB_H1;
    float* H2B  = smemB + OFFB_H2;
    float* H3B  = smemB + OFFB_H3;

    for (int i = tid; i < G1 * H1; i += NTB) {
        int g = i >> 5, k = i & 31;
        W1HI[k * G1 + 4 * (g & 31) + (g >> 5)] = w_hh1[i];
    }
    for (int i = tid; i < G2 * H1; i += NTB) {
        int g = i >> 5, k = i & 31;
        W2XI[k * G2 + 4 * (g & 15) + (g >> 4)] = w_ih2[i];
    }
    for (int i = tid; i < G2 * H2; i += NTB) {
        int g = i >> 4, k = i & 15;
        W2HI[k * G2 + 4 * (g & 15) + (g >> 4)] = w_hh2[i];
    }
    for (int i = tid; i < G2; i += NTB)
        B2I[4 * (i & 15) + (i >> 4)] = b_ih2[i] + b_hh2[i];
    for (int i = tid; i < G3 * H2; i += NTB) {
        int g = i >> 4, k = i & 15;
        W3XI[k * G3 + 4 * (g & 7) + (g >> 3)] = w_ih3[i];
    }
    for (int i = tid; i < G3 * H3; i += NTB) {
        int g = i >> 3, k = i & 7;
        W3HI[k * G3 + 4 * (g & 7) + (g >> 3)] = w_hh3[i];
    }
    for (int i = tid; i < G3; i += NTB)
        B3I[4 * (i & 7) + (i >> 3)] = b_ih3[i] + b_hh3[i];
    for (int i = tid; i < 2 * H1SZ; i += NTB) H1B[i] = 0.f;
    for (int i = tid; i < 2 * H2SZ; i += NTB) H2B[i] = 0.f;
    for (int i = tid; i < 2 * H3SZ; i += NTB) H3B[i] = 0.f;

    // group A (warps 0-7): L1, 1 j x 4 batch.
    // REMAP v2: warp spans 16 j x 2 batch-quads -> W1 LDS = 256B/warp/k (halved),
    // XG LDG stays coalesced (2 x 256B segments).
    const int widA = tid >> 5;
    const int j1 = (widA & 1) * 16 + (tid & 15);
    const int b1 = (widA >> 1) * 8 + ((tid >> 4) & 1) * 4;
    const int bg0 = cta * BTB + b1;
    float c1[4] = {0.f, 0.f, 0.f, 0.f};
    float4 xg[4];

    // group B (warps 8-15)
    const int tid2 = tid - 256;
    const int j2 = tid2 >> 4;
    const int b2 = (tid2 & 15) * 2;
    const int j3 = tid2 >> 5;
    const int b3 = tid2 & 31;
    float c2[2] = {0.f, 0.f};
    float c3 = 0.f;

    if (tid < 256) {
#pragma unroll
        for (int i = 0; i < 4; i++)
            xg[i] = *(const float4*)(g_xg + (size_t)(bg0 + i) * TT * G1 + 4 * j1);
    }
    __syncthreads();

    if (tid < 256)
        stage1_step(0, bg0, W1HI, H1B, xg, c1, j1, b1);
    __syncthreads();

    for (int t = 0; t < TT; ++t) {
        if (tid < 256) {
            if (t + 1 < TT)
                stage1_step(t + 1, bg0, W1HI, H1B, xg, c1, j1, b1);
        } else {
            const float* H1t = H1B + (t & 1) * H1SZ;
            const float* H2r = H2B + ((t + 1) & 1) * H2SZ;
            float* H2w = H2B + (t & 1) * H2SZ;
            const float* H3r = H3B + ((t + 1) & 1) * H3SZ;
            float* H3w = H3B + (t & 1) * H3SZ;

            {
                u64 acc[4];
                float4 bv4 = *(const float4*)(B2I + 4 * j2);
                acc[0] = pack2(bv4.x, bv4.x);
                acc[1] = pack2(bv4.y, bv4.y);
                acc[2] = pack2(bv4.z, bv4.z);
                acc[3] = pack2(bv4.w, bv4.w);
#pragma unroll 4
                for (int k = 0; k < H1; k++) {
                    const float* wr = W2XI + k * G2 + 4 * j2;
                    float4 w4 = *(const float4*)wr;
                    u64 xv = *(const u64*)(H1t + k * HP + b2);
                    acc[0] = fma2(xv, pack2(w4.x, w4.x), acc[0]);
                    acc[1] = fma2(xv, pack2(w4.y, w4.y), acc[1]);
                    acc[2] = fma2(xv, pack2(w4.z, w4.z), acc[2]);
                    acc[3] = fma2(xv, pack2(w4.w, w4.w), acc[3]);
                }
#pragma unroll 4
                for (int k = 0; k < H2; k++) {
                    const float* wr = W2HI + k * G2 + 4 * j2;
                    float4 w4 = *(const float4*)wr;
                    u64 xv = *(const u64*)(H2r + k * HP + b2);
                    acc[0] = fma2(xv, pack2(w4.x, w4.x), acc[0]);
                    acc[1] = fma2(xv, pack2(w4.y, w4.y), acc[1]);
                    acc[2] = fma2(xv, pack2(w4.z, w4.z), acc[2]);
                    acc[3] = fma2(xv, pack2(w4.w, w4.w), acc[3]);
                }
                float2 ai = u2f2(acc[0]);
                float2 af = u2f2(acc[1]);
                float2 ag = u2f2(acc[2]);
                float2 ao = u2f2(acc[3]);
                float h2v[2];
#pragma unroll
                for (int m = 0; m < 2; m++) {
                    float iv = sigf(m ? ai.y : ai.x);
                    float fv = sigf(m ? af.y : af.x);
                    float gv = tanhf_(m ? ag.y : ag.x);
                    float ov = sigf(m ? ao.y : ao.x);
                    float c = fv * c2[m] + iv * gv;
                    c2[m] = c;
                    h2v[m] = ov * tanhf_(c);
                }
                float2 hv; hv.x = h2v[0]; hv.y = h2v[1];
                *(float2*)(H2w + j2 * HP + b2) = hv;
            }
            asm volatile("bar.sync 1, 256;" ::: "memory");

            {
                u64 aif = *(const u64*)(B3I + 4 * j3);
                u64 ago = *(const u64*)(B3I + 4 * j3 + 2);
#pragma unroll 4
                for (int k = 0; k < H2; k++) {
                    ulonglong2 w = *(const ulonglong2*)(W3XI + k * G3 + 4 * j3);
                    float s = H2w[k * HP + b3];
                    u64 ss = pack2(s, s);
                    aif = fma2(ss, w.x, aif);
                    ago = fma2(ss, w.y, ago);
                }
#pragma unroll
                for (int k = 0; k < H3; k++) {
                    ulonglong2 w = *(const ulonglong2*)(W3HI + k * G3 + 4 * j3);
                    float s = H3r[k * HP + b3];
                    u64 ss = pack2(s, s);
                    aif = fma2(ss, w.x, aif);
                    ago = fma2(ss, w.y, ago);
                }
                float2 vif = u2f2(aif), vgo = u2f2(ago);
                float iv = sigf(vif.x);
                float fv = sigf(vif.y);
                float gv = tanhf_(vgo.x);
                float ov = sigf(vgo.y);
                float c = fv * c3 + iv * gv;
                c3 = c;
                H3w[j3 * HP + b3] = ov * tanhf_(c);
            }
        }
        __syncthreads();
    }

    if (tid < BTB) {
        const float* H3f = H3B + H3SZ;
        float acc = fc_b[0];
#pragma unroll
        for (int j = 0; j < H3; j++) acc += fc_w[j] * H3f[j * HP + tid];
        out[cta * BTB + tid] = acc;
    }
}

extern "C" void kernel_launch(void* const* d_in, const int* in_sizes, int n_in,
                              void* d_out, int out_size) {
    (void)in_sizes; (void)n_in; (void)out_size;
    const float* x     = (const float*)d_in[0];
    const float* w_ih1 = (const float*)d_in[1];
    const float* w_hh1 = (const float*)d_in[2];
    const float* b_ih1 = (const float*)d_in[3];
    const float* b_hh1 = (const float*)d_in[4];
    const float* w_ih2 = (const float*)d_in[5];
    const float* w_hh2 = (const float*)d_in[6];
    const float* b_ih2 = (const float*)d_in[7];
    const float* b_hh2 = (const float*)d_in[8];
    const float* w_ih3 = (const float*)d_in[9];
    const float* w_hh3 = (const float*)d_in[10];
    const float* b_ih3 = (const float*)d_in[11];
    const float* b_hh3 = (const float*)d_in[12];
    const float* fc_w  = (const float*)d_in[13];
    const float* fc_b  = (const float*)d_in[14];
    float* out = (float*)d_out;

    cudaFuncSetAttribute(lstm_phaseA_mma,
                         cudaFuncAttributeMaxDynamicSharedMemorySize, A_SMEM_BYTES);
    cudaFuncSetAttribute(lstm_phaseB,
                         cudaFuncAttributeMaxDynamicSharedMemorySize, B_SMEM_BYTES);

    lstm_phaseA_mma<<<NBLK_A, NTM_A, A_SMEM_BYTES>>>(x, w_ih1, b_ih1, b_hh1);
    lstm_phaseB<<<NCTA_B, NTB, B_SMEM_BYTES>>>(
        w_hh1, w_ih2, w_hh2, b_ih2, b_hh2,
        w_ih3, w_hh3, b_ih3, b_hh3, fc_w, fc_b, out);
}